// round 3
// baseline (speedup 1.0000x reference)
#include <cuda_runtime.h>
#include <math.h>

#define NL 6
#define NH 8
#define DM 512
#define DHS 64
#define NB 8
#define NT 1024
#define NF 32
#define NE 16
#define DFF 2048
#define NO 49
#define BT (NB*NT)
#define EPSV 1e-5f

// ---------------- scratch (device globals: no allocation allowed) ----------
__device__ float g_x [BT*DM];
__device__ float g_xn[BT*DM];
__device__ float g_q [BT*DM];
__device__ float g_k [BT*DM];
__device__ float g_v [BT*DM];
__device__ float g_o [BT*DM];
__device__ float g_h1[BT*DFF];
__device__ float g_wei[NB*NH*NT*NT];       // 256 MB attention scores
__device__ float g_scores[BT];
__device__ float g_aw[BT];
__device__ float g_part[NB*8*DM];

// ---------------- reductions ----------------
__device__ __forceinline__ float blockReduceSum(float v, float* sbuf) {
    int lane = threadIdx.x & 31, wid = threadIdx.x >> 5;
    #pragma unroll
    for (int o = 16; o > 0; o >>= 1) v += __shfl_down_sync(0xffffffffu, v, o);
    if (lane == 0) sbuf[wid] = v;
    __syncthreads();
    int nw = blockDim.x >> 5;
    v = (threadIdx.x < nw) ? sbuf[threadIdx.x] : 0.f;
    if (wid == 0) {
        #pragma unroll
        for (int o = 16; o > 0; o >>= 1) v += __shfl_down_sync(0xffffffffu, v, o);
        if (lane == 0) sbuf[0] = v;
    }
    __syncthreads();
    float r = sbuf[0];
    __syncthreads();
    return r;
}

__device__ __forceinline__ float blockReduceMax(float v, float* sbuf) {
    int lane = threadIdx.x & 31, wid = threadIdx.x >> 5;
    #pragma unroll
    for (int o = 16; o > 0; o >>= 1) v = fmaxf(v, __shfl_down_sync(0xffffffffu, v, o));
    if (lane == 0) sbuf[wid] = v;
    __syncthreads();
    int nw = blockDim.x >> 5;
    v = (threadIdx.x < nw) ? sbuf[threadIdx.x] : -3.0e38f;
    if (wid == 0) {
        #pragma unroll
        for (int o = 16; o > 0; o >>= 1) v = fmaxf(v, __shfl_down_sync(0xffffffffu, v, o));
        if (lane == 0) sbuf[0] = v;
    }
    __syncthreads();
    float r = sbuf[0];
    __syncthreads();
    return r;
}

// ---------------- embed + posenc ----------------
// x[b,t,d] = emb[code[b,t,d/16], d%16] + posenc(t,d)
__global__ void embed_kernel(const int* __restrict__ code,
                             const float* __restrict__ emb,
                             float* __restrict__ x) {
    int bt = blockIdx.x;                  // 0..BT-1
    int t  = bt & (NT - 1);
    int d0 = threadIdx.x * 4;             // 128 threads * 4 = 512
    const int* crow = code + (long long)bt * NF;
    float4 out;
    float* po = (float*)&out;
    #pragma unroll
    for (int j = 0; j < 4; j++) {
        int d = d0 + j;
        int f = d >> 4, e = d & 15;
        int c = crow[f];
        float df  = expf(-(float)(d & ~1) * (9.210340371976184f / 512.0f)); // ln(1e4)/D
        float ang = (float)t * df;
        float pe  = (d & 1) ? cosf(ang) : sinf(ang);
        po[j] = emb[c * NE + e] + pe;
    }
    *(float4*)(x + (long long)bt * DM + d0) = out;
}

// ---------------- layernorm ----------------
__global__ void ln_kernel(const float* __restrict__ in,
                          const float* __restrict__ g,
                          const float* __restrict__ b,
                          float* __restrict__ out) {
    __shared__ float red[32];
    int bt = blockIdx.x;
    int tid = threadIdx.x;                // 128 threads, 1 float4 each
    float4 v = *(const float4*)(in + (long long)bt * DM + tid * 4);
    float s = v.x + v.y + v.z + v.w;
    s = blockReduceSum(s, red);
    float mean = s * (1.0f / DM);
    float d0 = v.x - mean, d1 = v.y - mean, d2 = v.z - mean, d3 = v.w - mean;
    float s2 = d0*d0 + d1*d1 + d2*d2 + d3*d3;
    s2 = blockReduceSum(s2, red);
    float inv = rsqrtf(s2 * (1.0f / DM) + EPSV);
    float4 gg = *(const float4*)(g + tid * 4);
    float4 bb = *(const float4*)(b + tid * 4);
    float4 o;
    o.x = d0 * inv * gg.x + bb.x;
    o.y = d1 * inv * gg.y + bb.y;
    o.z = d2 * inv * gg.z + bb.z;
    o.w = d3 * inv * gg.w + bb.w;
    *(float4*)(out + (long long)bt * DM + tid * 4) = o;
}

// ---------------- generic batched GEMM ----------------
// C[m,n] = epi( alpha * sum_k A[m,k]*B[k,n] ), batched over grid.z with
// (outer,inner) strides: z -> zo = z/zdiv, zi = z%zdiv.
// flags: 1=transB (B[k,n] at B + n*ldb + k), 2=accumulate (C+=r), 4=gelu, 8=bias
#define GBM 128
#define GBN 64
#define GBK 16
#define GTM 8
#define GTN 4

__global__ void __launch_bounds__(256)
gemm_kernel(const float* __restrict__ A, const float* __restrict__ Bm,
            const float* __restrict__ bias, float* __restrict__ C,
            int K, int lda, int ldb, int ldc,
            long long aO, long long aI, long long bO, long long bI,
            long long cO, long long cI, int zdiv,
            int flags, float alpha) {
    int z = blockIdx.z;
    int zo = z / zdiv, zi = z - zo * zdiv;
    A  += zo * aO + zi * aI;
    Bm += zo * bO + zi * bI;
    C  += zo * cO + zi * cI;
    int m0 = blockIdx.y * GBM;
    int n0 = blockIdx.x * GBN;

    __shared__ float As[GBK][GBM];
    __shared__ float Bs[GBK][GBN];

    int tid = threadIdx.x;
    int tx = tid & 15, ty = tid >> 4;

    float acc[GTM][GTN];
    #pragma unroll
    for (int i = 0; i < GTM; i++)
        #pragma unroll
        for (int j = 0; j < GTN; j++) acc[i][j] = 0.f;

    bool transB = (flags & 1);

    for (int k0 = 0; k0 < K; k0 += GBK) {
        // A tile: 128x16 = 512 float4; 2 per thread
        #pragma unroll
        for (int i = 0; i < 2; i++) {
            int fid = tid + i * 256;
            int row = fid >> 2, kq = (fid & 3) << 2;
            float4 val = *(const float4*)(A + (long long)(m0 + row) * lda + k0 + kq);
            As[kq + 0][row] = val.x;
            As[kq + 1][row] = val.y;
            As[kq + 2][row] = val.z;
            As[kq + 3][row] = val.w;
        }
        // B tile: 16x64 = 256 float4; 1 per thread
        if (!transB) {
            int krow = tid >> 4, nq = (tid & 15) << 2;
            float4 val = *(const float4*)(Bm + (long long)(k0 + krow) * ldb + n0 + nq);
            *(float4*)(&Bs[krow][nq]) = val;
        } else {
            int ncol = tid >> 2, kq = (tid & 3) << 2;
            float4 val = *(const float4*)(Bm + (long long)(n0 + ncol) * ldb + k0 + kq);
            Bs[kq + 0][ncol] = val.x;
            Bs[kq + 1][ncol] = val.y;
            Bs[kq + 2][ncol] = val.z;
            Bs[kq + 3][ncol] = val.w;
        }
        __syncthreads();

        #pragma unroll
        for (int k = 0; k < GBK; k++) {
            float4 a0 = *(const float4*)(&As[k][ty * GTM]);
            float4 a1 = *(const float4*)(&As[k][ty * GTM + 4]);
            float4 bv = *(const float4*)(&Bs[k][tx * GTN]);
            float aa[GTM] = {a0.x, a0.y, a0.z, a0.w, a1.x, a1.y, a1.z, a1.w};
            float bb[GTN] = {bv.x, bv.y, bv.z, bv.w};
            #pragma unroll
            for (int i = 0; i < GTM; i++)
                #pragma unroll
                for (int j = 0; j < GTN; j++) acc[i][j] += aa[i] * bb[j];
        }
        __syncthreads();
    }

    bool accum = (flags & 2), doGelu = (flags & 4), hasBias = (flags & 8);
    #pragma unroll
    for (int i = 0; i < GTM; i++) {
        int m = m0 + ty * GTM + i;
        #pragma unroll
        for (int j = 0; j < GTN; j++) {
            int n = n0 + tx * GTN + j;
            float r = acc[i][j] * alpha;
            if (hasBias) r += bias[n];
            if (doGelu)  r = 0.5f * r * (1.0f + erff(r * 0.70710678118654752f));
            float* p = C + (long long)m * ldc + n;
            if (accum) r += *p;
            *p = r;
        }
    }
}

// ---------------- attention softmax (col mask + row mask) ----------------
__global__ void attn_softmax_kernel(float* __restrict__ wei,
                                    const int* __restrict__ lengths) {
    int t = blockIdx.x, h = blockIdx.y, b = blockIdx.z;
    int len = lengths[b];
    float* row = wei + (((long long)(b * NH + h)) * NT + t) * NT;
    int tid = threadIdx.x;                // 256 threads, 4 elems each
    int s0 = tid * 4;
    if (t >= len) {                       // row mask: zero entire row
        *(float4*)(row + s0) = make_float4(0.f, 0.f, 0.f, 0.f);
        return;
    }
    __shared__ float red[32];
    float4 v = *(const float4*)(row + s0);
    float vals[4] = {v.x, v.y, v.z, v.w};
    float m = -3.0e38f;
    #pragma unroll
    for (int j = 0; j < 4; j++) if (s0 + j < len) m = fmaxf(m, vals[j]);
    m = blockReduceMax(m, red);
    float e[4]; float sum = 0.f;
    #pragma unroll
    for (int j = 0; j < 4; j++) {
        e[j] = (s0 + j < len) ? expf(vals[j] - m) : 0.f;
        sum += e[j];
    }
    sum = blockReduceSum(sum, red);
    float inv = 1.0f / sum;
    float4 o = make_float4(e[0]*inv, e[1]*inv, e[2]*inv, e[3]*inv);
    *(float4*)(row + s0) = o;
}

// ---------------- pooling ----------------
__global__ void score_kernel(const float* __restrict__ xn,
                             const float* __restrict__ attn_w,
                             const float* __restrict__ attn_b,
                             float* __restrict__ scores) {
    __shared__ float red[32];
    int bt = blockIdx.x, tid = threadIdx.x;   // 128 threads
    float4 xv = *(const float4*)(xn + (long long)bt * DM + tid * 4);
    float4 wv = *(const float4*)(attn_w + tid * 4);
    float s = xv.x*wv.x + xv.y*wv.y + xv.z*wv.z + xv.w*wv.w;
    s = blockReduceSum(s, red);
    if (tid == 0) scores[bt] = s + attn_b[0];
}

__global__ void pool_softmax_kernel(const float* __restrict__ scores,
                                    const int* __restrict__ lengths,
                                    float* __restrict__ aw) {
    __shared__ float red[32];
    int b = blockIdx.x, t = threadIdx.x;      // 1024 threads
    int len = lengths[b];
    float s = (t < len) ? scores[b * NT + t] : -3.0e38f;
    float m = blockReduceMax(s, red);
    float e = (t < len) ? expf(s - m) : 0.f;
    float sum = blockReduceSum(e, red);
    aw[b * NT + t] = e / sum;
}

__global__ void pool_sum_kernel(const float* __restrict__ xn,
                                const float* __restrict__ aw,
                                float* __restrict__ part) {
    int b = blockIdx.y, c = blockIdx.x, d = threadIdx.x;   // 512 threads
    float acc = 0.f;
    int t0 = c * 128;
    for (int t = t0; t < t0 + 128; t++)
        acc += aw[b * NT + t] * xn[((long long)b * NT + t) * DM + d];
    part[(b * 8 + c) * DM + d] = acc;
}

__global__ void logits_kernel(const float* __restrict__ part,
                              const float* __restrict__ head_w,
                              const float* __restrict__ head_b,
                              float* __restrict__ out) {
    __shared__ float summ[DM];
    int b = blockIdx.x, o = threadIdx.x;      // 64 threads
    for (int d = o; d < DM; d += 64) {
        float s = 0.f;
        for (int c = 0; c < 8; c++) s += part[(b * 8 + c) * DM + d];
        summ[d] = s;
    }
    __syncthreads();
    if (o < NO) {
        float acc = head_b[o];
        for (int d = 0; d < DM; d++) acc += summ[d] * head_w[d * NO + o];
        out[b * NO + o] = acc;
    }
}

// ---------------- host launcher ----------------
static void gemm(const float* A, const float* B, const float* bias, float* C,
                 int M, int N, int K, int lda, int ldb, int ldc,
                 long long aO, long long aI, long long bO, long long bI,
                 long long cO, long long cI, int zdiv, int z,
                 int flags, float alpha) {
    dim3 grid(N / GBN, M / GBM, z);
    gemm_kernel<<<grid, 256>>>(A, B, bias, C, K, lda, ldb, ldc,
                               aO, aI, bO, bI, cO, cI, zdiv, flags, alpha);
}

extern "C" void kernel_launch(void* const* d_in, const int* in_sizes, int n_in,
                              void* d_out, int out_size) {
    const int*   code    = (const int*)  d_in[0];
    const int*   lengths = (const int*)  d_in[1];
    const float* emb     = (const float*)d_in[2];
    const float* Wq      = (const float*)d_in[3];
    const float* Wk      = (const float*)d_in[4];
    const float* Wv      = (const float*)d_in[5];
    const float* Wo      = (const float*)d_in[6];
    const float* bo      = (const float*)d_in[7];
    const float* W1      = (const float*)d_in[8];
    const float* b1      = (const float*)d_in[9];
    const float* W2      = (const float*)d_in[10];
    const float* b2      = (const float*)d_in[11];
    const float* ln1_g   = (const float*)d_in[12];
    const float* ln1_b   = (const float*)d_in[13];
    const float* ln2_g   = (const float*)d_in[14];
    const float* ln2_b   = (const float*)d_in[15];
    const float* lnf_g   = (const float*)d_in[16];
    const float* lnf_b   = (const float*)d_in[17];
    const float* attn_w  = (const float*)d_in[18];
    const float* attn_b  = (const float*)d_in[19];
    const float* head_w  = (const float*)d_in[20];
    const float* head_b  = (const float*)d_in[21];
    float* out = (float*)d_out;

    float *x, *xn, *q, *k, *v, *o, *h1, *wei, *scr, *aw, *part;
    cudaGetSymbolAddress((void**)&x,   g_x);
    cudaGetSymbolAddress((void**)&xn,  g_xn);
    cudaGetSymbolAddress((void**)&q,   g_q);
    cudaGetSymbolAddress((void**)&k,   g_k);
    cudaGetSymbolAddress((void**)&v,   g_v);
    cudaGetSymbolAddress((void**)&o,   g_o);
    cudaGetSymbolAddress((void**)&h1,  g_h1);
    cudaGetSymbolAddress((void**)&wei, g_wei);
    cudaGetSymbolAddress((void**)&scr, g_scores);
    cudaGetSymbolAddress((void**)&aw,  g_aw);
    cudaGetSymbolAddress((void**)&part,g_part);

    const long long sBH = (long long)NT * DM;      // 524288: per-batch stride in q/k/v/x
    const long long sTT = (long long)NT * NT;      // 1048576: per-head stride in wei

    embed_kernel<<<BT, 128>>>(code, emb, x);

    for (int l = 0; l < NL; l++) {
        const float* Wql = Wq + (long long)l * NH * DM * DHS;
        const float* Wkl = Wk + (long long)l * NH * DM * DHS;
        const float* Wvl = Wv + (long long)l * NH * DM * DHS;
        const float* Wol = Wo + (long long)l * DM * DM;
        const float* W1l = W1 + (long long)l * DM * DFF;
        const float* W2l = W2 + (long long)l * DFF * DM;

        ln_kernel<<<BT, 128>>>(x, ln1_g + l * DM, ln1_b + l * DM, xn);

        // QKV: batched over heads (z=8): A shared, B = per-head [D,HS], C cols h*64..
        gemm(xn, Wql, nullptr, q, BT, DHS, DM, DM, DHS, DM,
             0, 0, 0, (long long)DM * DHS, 0, DHS, 8, 8, 0, 1.0f);
        gemm(xn, Wkl, nullptr, k, BT, DHS, DM, DM, DHS, DM,
             0, 0, 0, (long long)DM * DHS, 0, DHS, 8, 8, 0, 1.0f);
        gemm(xn, Wvl, nullptr, v, BT, DHS, DM, DM, DHS, DM,
             0, 0, 0, (long long)DM * DHS, 0, DHS, 8, 8, 0, 1.0f);

        // scores = scale * Q K^T, batched over (b,h): z=64, zdiv=8
        gemm(q, k, nullptr, wei, NT, NT, DHS, DM, DM, NT,
             sBH, DHS, sBH, DHS, NH * sTT, sTT, 8, NB * NH,
             1 /*transB*/, 0.125f);

        attn_softmax_kernel<<<dim3(NT, NH, NB), 256>>>(wei, lengths);

        // O = P V, batched over (b,h)
        gemm(wei, v, nullptr, o, NT, DHS, NT, NT, DM, DM,
             NH * sTT, sTT, sBH, DHS, sBH, DHS, 8, NB * NH, 0, 1.0f);

        // x += O @ Wo + bo
        gemm(o, Wol, bo + l * DM, x, BT, DM, DM, DM, DM, DM,
             0, 0, 0, 0, 0, 0, 1, 1, 2 | 8, 1.0f);

        ln_kernel<<<BT, 128>>>(x, ln2_g + l * DM, ln2_b + l * DM, xn);

        // h1 = gelu(xn @ W1 + b1)
        gemm(xn, W1l, b1 + l * DFF, h1, BT, DFF, DM, DM, DFF, DFF,
             0, 0, 0, 0, 0, 0, 1, 1, 4 | 8, 1.0f);

        // x += h1 @ W2 + b2
        gemm(h1, W2l, b2 + l * DM, x, BT, DM, DFF, DFF, DM, DM,
             0, 0, 0, 0, 0, 0, 1, 1, 2 | 8, 1.0f);
    }

    ln_kernel<<<BT, 128>>>(x, lnf_g, lnf_b, xn);
    score_kernel<<<BT, 128>>>(xn, attn_w, attn_b, scr);
    pool_softmax_kernel<<<NB, 1024>>>(scr, lengths, aw);
    pool_sum_kernel<<<dim3(8, NB), 512>>>(xn, aw, part);
    logits_kernel<<<NB, 64>>>(part, head_w, head_b, out);
}

// round 4
// speedup vs baseline: 2.2319x; 2.2319x over previous
#include <cuda_runtime.h>
#include <math.h>
#include <stdint.h>

#define NL 6
#define NH 8
#define DM 512
#define DHS 64
#define NB 8
#define NT 1024
#define NF 32
#define NE 16
#define DFF 2048
#define NO 49
#define BT (NB*NT)
#define EPSV 1e-5f

// ---------------- scratch (device globals: no allocation allowed) ----------
__device__ float g_x [BT*DM];
__device__ float g_xn[BT*DM];
__device__ float g_q [BT*DM];
__device__ float g_k [BT*DM];
__device__ float g_v [BT*DM];
__device__ float g_o [BT*DM];
__device__ float g_h1[BT*DFF];
__device__ float g_wei[NB*NH*NT*NT];       // 256 MB attention scores
__device__ float g_scores[BT];
__device__ float g_aw[BT];
__device__ float g_part[NB*8*DM];

// ---------------- reductions ----------------
__device__ __forceinline__ float blockReduceSum(float v, float* sbuf) {
    int lane = threadIdx.x & 31, wid = threadIdx.x >> 5;
    #pragma unroll
    for (int o = 16; o > 0; o >>= 1) v += __shfl_down_sync(0xffffffffu, v, o);
    if (lane == 0) sbuf[wid] = v;
    __syncthreads();
    int nw = blockDim.x >> 5;
    v = (threadIdx.x < nw) ? sbuf[threadIdx.x] : 0.f;
    if (wid == 0) {
        #pragma unroll
        for (int o = 16; o > 0; o >>= 1) v += __shfl_down_sync(0xffffffffu, v, o);
        if (lane == 0) sbuf[0] = v;
    }
    __syncthreads();
    float r = sbuf[0];
    __syncthreads();
    return r;
}

__device__ __forceinline__ float blockReduceMax(float v, float* sbuf) {
    int lane = threadIdx.x & 31, wid = threadIdx.x >> 5;
    #pragma unroll
    for (int o = 16; o > 0; o >>= 1) v = fmaxf(v, __shfl_down_sync(0xffffffffu, v, o));
    if (lane == 0) sbuf[wid] = v;
    __syncthreads();
    int nw = blockDim.x >> 5;
    v = (threadIdx.x < nw) ? sbuf[threadIdx.x] : -3.0e38f;
    if (wid == 0) {
        #pragma unroll
        for (int o = 16; o > 0; o >>= 1) v = fmaxf(v, __shfl_down_sync(0xffffffffu, v, o));
        if (lane == 0) sbuf[0] = v;
    }
    __syncthreads();
    float r = sbuf[0];
    __syncthreads();
    return r;
}

// ---------------- embed + posenc ----------------
__global__ void embed_kernel(const int* __restrict__ code,
                             const float* __restrict__ emb,
                             float* __restrict__ x) {
    int bt = blockIdx.x;
    int t  = bt & (NT - 1);
    int d0 = threadIdx.x * 4;
    const int* crow = code + (long long)bt * NF;
    float4 out;
    float* po = (float*)&out;
    #pragma unroll
    for (int j = 0; j < 4; j++) {
        int d = d0 + j;
        int f = d >> 4, e = d & 15;
        int c = crow[f];
        float df  = expf(-(float)(d & ~1) * (9.210340371976184f / 512.0f));
        float ang = (float)t * df;
        float pe  = (d & 1) ? cosf(ang) : sinf(ang);
        po[j] = emb[c * NE + e] + pe;
    }
    *(float4*)(x + (long long)bt * DM + d0) = out;
}

// ---------------- layernorm ----------------
__global__ void ln_kernel(const float* __restrict__ in,
                          const float* __restrict__ g,
                          const float* __restrict__ b,
                          float* __restrict__ out) {
    __shared__ float red[32];
    int bt = blockIdx.x;
    int tid = threadIdx.x;
    float4 v = *(const float4*)(in + (long long)bt * DM + tid * 4);
    float s = v.x + v.y + v.z + v.w;
    s = blockReduceSum(s, red);
    float mean = s * (1.0f / DM);
    float d0 = v.x - mean, d1 = v.y - mean, d2 = v.z - mean, d3 = v.w - mean;
    float s2 = d0*d0 + d1*d1 + d2*d2 + d3*d3;
    s2 = blockReduceSum(s2, red);
    float inv = rsqrtf(s2 * (1.0f / DM) + EPSV);
    float4 gg = *(const float4*)(g + tid * 4);
    float4 bb = *(const float4*)(b + tid * 4);
    float4 o;
    o.x = d0 * inv * gg.x + bb.x;
    o.y = d1 * inv * gg.y + bb.y;
    o.z = d2 * inv * gg.z + bb.z;
    o.w = d3 * inv * gg.w + bb.w;
    *(float4*)(out + (long long)bt * DM + tid * 4) = o;
}

// ---------------- TF32 tensor-core batched GEMM ----------------
// C[m,n] = epi( alpha * sum_k A[m,k]*B[k,n] ), batched over grid.z with
// (outer,inner) strides. flags: 1=transB, 2=accumulate, 4=gelu, 8=bias
#define GBM 128
#define GBN 64
#define GBK 32
#define APAD 36   // bank(As[m][k]) = (4*m + k) % 32 within fragment -> conflict-free
#define BPAD 72   // bank(Bs[k][n]) = (8*k + n) % 32 within fragment -> conflict-free

__device__ __forceinline__ uint32_t f2tf(float x) {
    uint32_t r;
    asm("cvt.rna.tf32.f32 %0, %1;" : "=r"(r) : "f"(x));
    return r;
}

__device__ __forceinline__ void mma_tf32(float c[4], const uint32_t a[4], const uint32_t b[2]) {
    asm volatile(
        "mma.sync.aligned.m16n8k8.row.col.f32.tf32.tf32.f32 "
        "{%0,%1,%2,%3}, {%4,%5,%6,%7}, {%8,%9}, {%0,%1,%2,%3};"
        : "+f"(c[0]), "+f"(c[1]), "+f"(c[2]), "+f"(c[3])
        : "r"(a[0]), "r"(a[1]), "r"(a[2]), "r"(a[3]), "r"(b[0]), "r"(b[1]));
}

__global__ void __launch_bounds__(256)
gemm_tc_kernel(const float* __restrict__ A, const float* __restrict__ Bm,
               const float* __restrict__ bias, float* __restrict__ C,
               int K, int lda, int ldb, int ldc,
               long long aO, long long aI, long long bO, long long bI,
               long long cO, long long cI, int zdiv,
               int flags, float alpha) {
    int z = blockIdx.z;
    int zo = z / zdiv, zi = z - zo * zdiv;
    A  += zo * aO + zi * aI;
    Bm += zo * bO + zi * bI;
    C  += zo * cO + zi * cI;
    int m0 = blockIdx.y * GBM;
    int n0 = blockIdx.x * GBN;

    __shared__ uint32_t As[GBM][APAD];   // 128 x 32 used (tf32 bits)
    __shared__ uint32_t Bs[GBK][BPAD];   // 32 x 64 used

    int tid  = threadIdx.x;
    int lane = tid & 31, warp = tid >> 5;
    int wm = warp & 3;        // warp row: 4 warps * 32 rows = 128
    int wn = warp >> 2;       // warp col: 2 warps * 32 cols = 64
    int grp = lane >> 2, qid = lane & 3;

    float acc[2][4][4];
    #pragma unroll
    for (int i = 0; i < 2; i++)
        #pragma unroll
        for (int j = 0; j < 4; j++)
            #pragma unroll
            for (int r = 0; r < 4; r++) acc[i][j][r] = 0.f;

    bool transB = (flags & 1);

    for (int k0 = 0; k0 < K; k0 += GBK) {
        // ---- A tile: 128x32, 4 float4 per thread, vectorized STS (aligned: 36*4=144=9*16)
        #pragma unroll
        for (int i = 0; i < 4; i++) {
            int fid = tid + i * 256;
            int m = fid >> 3, kq = (fid & 7) << 2;
            float4 v = *(const float4*)(A + (long long)(m0 + m) * lda + k0 + kq);
            uint4 t;
            t.x = f2tf(v.x); t.y = f2tf(v.y); t.z = f2tf(v.z); t.w = f2tf(v.w);
            *(uint4*)(&As[m][kq]) = t;
        }
        // ---- B tile: 32x64
        if (!transB) {
            #pragma unroll
            for (int i = 0; i < 2; i++) {
                int fid = tid + i * 256;
                int k = fid >> 4, nq = (fid & 15) << 2;
                float4 v = *(const float4*)(Bm + (long long)(k0 + k) * ldb + n0 + nq);
                uint4 t;
                t.x = f2tf(v.x); t.y = f2tf(v.y); t.z = f2tf(v.z); t.w = f2tf(v.w);
                *(uint4*)(&Bs[k][nq]) = t;
            }
        } else {
            // B[k,n] = Bm[n, k]; n = lane within warp -> conflict-free scalar stores
            #pragma unroll
            for (int i = 0; i < 2; i++) {
                int fid = tid + i * 256;
                int n = fid & 63, kq = ((fid >> 6) & 7) << 2;
                float4 v = *(const float4*)(Bm + (long long)(n0 + n) * ldb + k0 + kq);
                Bs[kq + 0][n] = f2tf(v.x);
                Bs[kq + 1][n] = f2tf(v.y);
                Bs[kq + 2][n] = f2tf(v.z);
                Bs[kq + 3][n] = f2tf(v.w);
            }
        }
        __syncthreads();

        #pragma unroll
        for (int ks = 0; ks < 4; ks++) {
            int kk = ks * 8;
            uint32_t af[2][4], bf[4][2];
            #pragma unroll
            for (int i = 0; i < 2; i++) {
                int am = wm * 32 + i * 16 + grp;
                af[i][0] = As[am    ][kk + qid];
                af[i][1] = As[am + 8][kk + qid];
                af[i][2] = As[am    ][kk + qid + 4];
                af[i][3] = As[am + 8][kk + qid + 4];
            }
            #pragma unroll
            for (int j = 0; j < 4; j++) {
                int bn = wn * 32 + j * 8 + grp;
                bf[j][0] = Bs[kk + qid    ][bn];
                bf[j][1] = Bs[kk + qid + 4][bn];
            }
            #pragma unroll
            for (int i = 0; i < 2; i++)
                #pragma unroll
                for (int j = 0; j < 4; j++)
                    mma_tf32(acc[i][j], af[i], bf[j]);
        }
        __syncthreads();
    }

    // ---- epilogue
    bool accum = (flags & 2), doGelu = (flags & 4), hasBias = (flags & 8);
    #pragma unroll
    for (int i = 0; i < 2; i++) {
        #pragma unroll
        for (int j = 0; j < 4; j++) {
            int r0  = m0 + wm * 32 + i * 16 + grp;
            int col = n0 + wn * 32 + j * 8 + qid * 2;
            float bv0 = 0.f, bv1 = 0.f;
            if (hasBias) { bv0 = bias[col]; bv1 = bias[col + 1]; }
            #pragma unroll
            for (int h = 0; h < 2; h++) {      // h=0 -> row r0, h=1 -> row r0+8
                int r = r0 + h * 8;
                float v0 = acc[i][j][h * 2 + 0] * alpha + bv0;
                float v1 = acc[i][j][h * 2 + 1] * alpha + bv1;
                if (doGelu) {
                    v0 = 0.5f * v0 * (1.0f + erff(v0 * 0.70710678118654752f));
                    v1 = 0.5f * v1 * (1.0f + erff(v1 * 0.70710678118654752f));
                }
                float* p = C + (long long)r * ldc + col;
                if (accum) {
                    float2 old = *(float2*)p;
                    v0 += old.x; v1 += old.y;
                }
                float2 o2 = make_float2(v0, v1);
                *(float2*)p = o2;
            }
        }
    }
}

// ---------------- attention softmax (col mask + row mask) ----------------
__global__ void attn_softmax_kernel(float* __restrict__ wei,
                                    const int* __restrict__ lengths) {
    int t = blockIdx.x, h = blockIdx.y, b = blockIdx.z;
    int len = lengths[b];
    float* row = wei + (((long long)(b * NH + h)) * NT + t) * NT;
    int tid = threadIdx.x;
    int s0 = tid * 4;
    if (t >= len) {
        *(float4*)(row + s0) = make_float4(0.f, 0.f, 0.f, 0.f);
        return;
    }
    __shared__ float red[32];
    float4 v = *(const float4*)(row + s0);
    float vals[4] = {v.x, v.y, v.z, v.w};
    float m = -3.0e38f;
    #pragma unroll
    for (int j = 0; j < 4; j++) if (s0 + j < len) m = fmaxf(m, vals[j]);
    m = blockReduceMax(m, red);
    float e[4]; float sum = 0.f;
    #pragma unroll
    for (int j = 0; j < 4; j++) {
        e[j] = (s0 + j < len) ? expf(vals[j] - m) : 0.f;
        sum += e[j];
    }
    sum = blockReduceSum(sum, red);
    float inv = 1.0f / sum;
    float4 o = make_float4(e[0]*inv, e[1]*inv, e[2]*inv, e[3]*inv);
    *(float4*)(row + s0) = o;
}

// ---------------- pooling ----------------
__global__ void score_kernel(const float* __restrict__ xn,
                             const float* __restrict__ attn_w,
                             const float* __restrict__ attn_b,
                             float* __restrict__ scores) {
    __shared__ float red[32];
    int bt = blockIdx.x, tid = threadIdx.x;
    float4 xv = *(const float4*)(xn + (long long)bt * DM + tid * 4);
    float4 wv = *(const float4*)(attn_w + tid * 4);
    float s = xv.x*wv.x + xv.y*wv.y + xv.z*wv.z + xv.w*wv.w;
    s = blockReduceSum(s, red);
    if (tid == 0) scores[bt] = s + attn_b[0];
}

__global__ void pool_softmax_kernel(const float* __restrict__ scores,
                                    const int* __restrict__ lengths,
                                    float* __restrict__ aw) {
    __shared__ float red[32];
    int b = blockIdx.x, t = threadIdx.x;
    int len = lengths[b];
    float s = (t < len) ? scores[b * NT + t] : -3.0e38f;
    float m = blockReduceMax(s, red);
    float e = (t < len) ? expf(s - m) : 0.f;
    float sum = blockReduceSum(e, red);
    aw[b * NT + t] = e / sum;
}

__global__ void pool_sum_kernel(const float* __restrict__ xn,
                                const float* __restrict__ aw,
                                float* __restrict__ part) {
    int b = blockIdx.y, c = blockIdx.x, d = threadIdx.x;
    float acc = 0.f;
    int t0 = c * 128;
    for (int t = t0; t < t0 + 128; t++)
        acc += aw[b * NT + t] * xn[((long long)b * NT + t) * DM + d];
    part[(b * 8 + c) * DM + d] = acc;
}

__global__ void logits_kernel(const float* __restrict__ part,
                              const float* __restrict__ head_w,
                              const float* __restrict__ head_b,
                              float* __restrict__ out) {
    __shared__ float summ[DM];
    int b = blockIdx.x, o = threadIdx.x;
    for (int d = o; d < DM; d += 64) {
        float s = 0.f;
        for (int c = 0; c < 8; c++) s += part[(b * 8 + c) * DM + d];
        summ[d] = s;
    }
    __syncthreads();
    if (o < NO) {
        float acc = head_b[o];
        for (int d = 0; d < DM; d++) acc += summ[d] * head_w[d * NO + o];
        out[b * NO + o] = acc;
    }
}

// ---------------- host launcher ----------------
static void gemm(const float* A, const float* B, const float* bias, float* C,
                 int M, int N, int K, int lda, int ldb, int ldc,
                 long long aO, long long aI, long long bO, long long bI,
                 long long cO, long long cI, int zdiv, int z,
                 int flags, float alpha) {
    dim3 grid(N / GBN, M / GBM, z);
    gemm_tc_kernel<<<grid, 256>>>(A, B, bias, C, K, lda, ldb, ldc,
                                  aO, aI, bO, bI, cO, cI, zdiv, flags, alpha);
}

extern "C" void kernel_launch(void* const* d_in, const int* in_sizes, int n_in,
                              void* d_out, int out_size) {
    const int*   code    = (const int*)  d_in[0];
    const int*   lengths = (const int*)  d_in[1];
    const float* emb     = (const float*)d_in[2];
    const float* Wq      = (const float*)d_in[3];
    const float* Wk      = (const float*)d_in[4];
    const float* Wv      = (const float*)d_in[5];
    const float* Wo      = (const float*)d_in[6];
    const float* bo      = (const float*)d_in[7];
    const float* W1      = (const float*)d_in[8];
    const float* b1      = (const float*)d_in[9];
    const float* W2      = (const float*)d_in[10];
    const float* b2      = (const float*)d_in[11];
    const float* ln1_g   = (const float*)d_in[12];
    const float* ln1_b   = (const float*)d_in[13];
    const float* ln2_g   = (const float*)d_in[14];
    const float* ln2_b   = (const float*)d_in[15];
    const float* lnf_g   = (const float*)d_in[16];
    const float* lnf_b   = (const float*)d_in[17];
    const float* attn_w  = (const float*)d_in[18];
    const float* attn_b  = (const float*)d_in[19];
    const float* head_w  = (const float*)d_in[20];
    const float* head_b  = (const float*)d_in[21];
    float* out = (float*)d_out;

    float *x, *xn, *q, *k, *v, *o, *h1, *wei, *scr, *aw, *part;
    cudaGetSymbolAddress((void**)&x,   g_x);
    cudaGetSymbolAddress((void**)&xn,  g_xn);
    cudaGetSymbolAddress((void**)&q,   g_q);
    cudaGetSymbolAddress((void**)&k,   g_k);
    cudaGetSymbolAddress((void**)&v,   g_v);
    cudaGetSymbolAddress((void**)&o,   g_o);
    cudaGetSymbolAddress((void**)&h1,  g_h1);
    cudaGetSymbolAddress((void**)&wei, g_wei);
    cudaGetSymbolAddress((void**)&scr, g_scores);
    cudaGetSymbolAddress((void**)&aw,  g_aw);
    cudaGetSymbolAddress((void**)&part,g_part);

    const long long sBH = (long long)NT * DM;
    const long long sTT = (long long)NT * NT;

    embed_kernel<<<BT, 128>>>(code, emb, x);

    for (int l = 0; l < NL; l++) {
        const float* Wql = Wq + (long long)l * NH * DM * DHS;
        const float* Wkl = Wk + (long long)l * NH * DM * DHS;
        const float* Wvl = Wv + (long long)l * NH * DM * DHS;
        const float* Wol = Wo + (long long)l * DM * DM;
        const float* W1l = W1 + (long long)l * DM * DFF;
        const float* W2l = W2 + (long long)l * DFF * DM;

        ln_kernel<<<BT, 128>>>(x, ln1_g + l * DM, ln1_b + l * DM, xn);

        // QKV: batched over heads (z=8)
        gemm(xn, Wql, nullptr, q, BT, DHS, DM, DM, DHS, DM,
             0, 0, 0, (long long)DM * DHS, 0, DHS, 8, 8, 0, 1.0f);
        gemm(xn, Wkl, nullptr, k, BT, DHS, DM, DM, DHS, DM,
             0, 0, 0, (long long)DM * DHS, 0, DHS, 8, 8, 0, 1.0f);
        gemm(xn, Wvl, nullptr, v, BT, DHS, DM, DM, DHS, DM,
             0, 0, 0, (long long)DM * DHS, 0, DHS, 8, 8, 0, 1.0f);

        // scores = scale * Q K^T, batched over (b,h): z=64, zdiv=8
        gemm(q, k, nullptr, wei, NT, NT, DHS, DM, DM, NT,
             sBH, DHS, sBH, DHS, NH * sTT, sTT, 8, NB * NH,
             1 /*transB*/, 0.125f);

        attn_softmax_kernel<<<dim3(NT, NH, NB), 256>>>(wei, lengths);

        // O = P V, batched over (b,h)
        gemm(wei, v, nullptr, o, NT, DHS, NT, NT, DM, DM,
             NH * sTT, sTT, sBH, DHS, sBH, DHS, 8, NB * NH, 0, 1.0f);

        // x += O @ Wo + bo
        gemm(o, Wol, bo + l * DM, x, BT, DM, DM, DM, DM, DM,
             0, 0, 0, 0, 0, 0, 1, 1, 2 | 8, 1.0f);

        ln_kernel<<<BT, 128>>>(x, ln2_g + l * DM, ln2_b + l * DM, xn);

        // h1 = gelu(xn @ W1 + b1)
        gemm(xn, W1l, b1 + l * DFF, h1, BT, DFF, DM, DM, DFF, DFF,
             0, 0, 0, 0, 0, 0, 1, 1, 4 | 8, 1.0f);

        // x += h1 @ W2 + b2
        gemm(h1, W2l, b2 + l * DM, x, BT, DM, DFF, DFF, DM, DM,
             0, 0, 0, 0, 0, 0, 1, 1, 2 | 8, 1.0f);
    }

    ln_kernel<<<BT, 128>>>(x, lnf_g, lnf_b, xn);
    score_kernel<<<BT, 128>>>(xn, attn_w, attn_b, scr);
    pool_softmax_kernel<<<NB, 1024>>>(scr, lengths, aw);
    pool_sum_kernel<<<dim3(8, NB), 512>>>(xn, aw, part);
    logits_kernel<<<NB, 64>>>(part, head_w, head_b, out);
}

// round 6
// speedup vs baseline: 2.5138x; 1.1263x over previous
#include <cuda_runtime.h>
#include <math.h>
#include <stdint.h>

#define NL 6
#define NH 8
#define DM 512
#define DHS 64
#define NB 8
#define NT 1024
#define NF 32
#define NE 16
#define DFF 2048
#define NO 49
#define BT (NB*NT)
#define EPSV 1e-5f

// ---------------- scratch (device globals: no allocation allowed) ----------
__device__ float g_x [BT*DM];
__device__ float g_xn[BT*DM];
__device__ float g_q [BT*DM];
__device__ float g_k [BT*DM];      // used as kT[b][h][e][t]
__device__ float g_v [BT*DM];
__device__ float g_o [BT*DM];
__device__ float g_h1[BT*DFF];
__device__ float g_wei[NB*NH*NT*NT];       // 256 MB attention scores
__device__ float g_scores[BT];
__device__ float g_aw[BT];
__device__ float g_part[NB*8*DM];
__device__ float g_Wrep[3*NL*DM*DM];       // repacked Wq/Wk/Wv: [w][l][d][h*64+e]

// ---------------- reductions ----------------
__device__ __forceinline__ float blockReduceSum(float v, float* sbuf) {
    int lane = threadIdx.x & 31, wid = threadIdx.x >> 5;
    #pragma unroll
    for (int o = 16; o > 0; o >>= 1) v += __shfl_down_sync(0xffffffffu, v, o);
    if (lane == 0) sbuf[wid] = v;
    __syncthreads();
    int nw = blockDim.x >> 5;
    v = (threadIdx.x < nw) ? sbuf[threadIdx.x] : 0.f;
    if (wid == 0) {
        #pragma unroll
        for (int o = 16; o > 0; o >>= 1) v += __shfl_down_sync(0xffffffffu, v, o);
        if (lane == 0) sbuf[0] = v;
    }
    __syncthreads();
    float r = sbuf[0];
    __syncthreads();
    return r;
}

__device__ __forceinline__ float blockReduceMax(float v, float* sbuf) {
    int lane = threadIdx.x & 31, wid = threadIdx.x >> 5;
    #pragma unroll
    for (int o = 16; o > 0; o >>= 1) v = fmaxf(v, __shfl_down_sync(0xffffffffu, v, o));
    if (lane == 0) sbuf[wid] = v;
    __syncthreads();
    int nw = blockDim.x >> 5;
    v = (threadIdx.x < nw) ? sbuf[threadIdx.x] : -3.0e38f;
    if (wid == 0) {
        #pragma unroll
        for (int o = 16; o > 0; o >>= 1) v = fmaxf(v, __shfl_down_sync(0xffffffffu, v, o));
        if (lane == 0) sbuf[0] = v;
    }
    __syncthreads();
    float r = sbuf[0];
    __syncthreads();
    return r;
}

// ---------------- weight repack ----------------
// out[w][l][d][h*64+e] = W_w[l][h][d][e]
__global__ void repack_kernel(const float* __restrict__ Wq,
                              const float* __restrict__ Wk,
                              const float* __restrict__ Wv,
                              float* __restrict__ out) {
    int idx = blockIdx.x * 256 + threadIdx.x;      // 0 .. NL*DM*DM-1
    int w = blockIdx.y;
    int n = idx & 511;
    int h = n >> 6, e = n & 63;
    int ld = idx >> 9;
    int d = ld & 511, l = ld >> 9;
    const float* W = (w == 0) ? Wq : (w == 1) ? Wk : Wv;
    out[(long long)w * NL * DM * DM + idx] =
        W[(((long long)(l * NH + h)) * DM + d) * DHS + e];
}

// ---------------- embed + posenc ----------------
__global__ void embed_kernel(const int* __restrict__ code,
                             const float* __restrict__ emb,
                             float* __restrict__ x) {
    int bt = blockIdx.x;
    int t  = bt & (NT - 1);
    int d0 = threadIdx.x * 4;
    const int* crow = code + (long long)bt * NF;
    float4 out;
    float* po = (float*)&out;
    #pragma unroll
    for (int j = 0; j < 4; j++) {
        int d = d0 + j;
        int f = d >> 4, e = d & 15;
        int c = crow[f];
        float df  = expf(-(float)(d & ~1) * (9.210340371976184f / 512.0f));
        float ang = (float)t * df;
        float pe  = (d & 1) ? cosf(ang) : sinf(ang);
        po[j] = emb[c * NE + e] + pe;
    }
    *(float4*)(x + (long long)bt * DM + d0) = out;
}

// ---------------- layernorm ----------------
__global__ void ln_kernel(const float* __restrict__ in,
                          const float* __restrict__ g,
                          const float* __restrict__ b,
                          float* __restrict__ out) {
    __shared__ float red[32];
    int bt = blockIdx.x;
    int tid = threadIdx.x;
    float4 v = *(const float4*)(in + (long long)bt * DM + tid * 4);
    float s = v.x + v.y + v.z + v.w;
    s = blockReduceSum(s, red);
    float mean = s * (1.0f / DM);
    float d0 = v.x - mean, d1 = v.y - mean, d2 = v.z - mean, d3 = v.w - mean;
    float s2 = d0*d0 + d1*d1 + d2*d2 + d3*d3;
    s2 = blockReduceSum(s2, red);
    float inv = rsqrtf(s2 * (1.0f / DM) + EPSV);
    float4 gg = *(const float4*)(g + tid * 4);
    float4 bb = *(const float4*)(b + tid * 4);
    float4 o;
    o.x = d0 * inv * gg.x + bb.x;
    o.y = d1 * inv * gg.y + bb.y;
    o.z = d2 * inv * gg.z + bb.z;
    o.w = d3 * inv * gg.w + bb.w;
    *(float4*)(out + (long long)bt * DM + tid * 4) = o;
}

// ---------------- TF32 tensor-core batched GEMM (cp.async pipelined) -------
// C = epi( alpha * A @ B ), batched over grid.z: zo=z/zdiv, zi=z%zdiv.
// flags: 2=accumulate, 4=gelu, 8=bias.  TRANSC: C[col*ldc + row] plain store.
// BM=128, BK=16 always. BN template = 64 or 128.
#define APAD 20    // As row = 80B (16B-aligned); frag bank = (4*(5g+?)..) conflict-free

__device__ __forceinline__ uint32_t f2tf(float x) {
    uint32_t r;
    asm("cvt.rna.tf32.f32 %0, %1;" : "=r"(r) : "f"(x));
    return r;
}

__device__ __forceinline__ void mma_tf32(float c[4], const uint32_t a[4], const uint32_t b[2]) {
    asm volatile(
        "mma.sync.aligned.m16n8k8.row.col.f32.tf32.tf32.f32 "
        "{%0,%1,%2,%3}, {%4,%5,%6,%7}, {%8,%9}, {%0,%1,%2,%3};"
        : "+f"(c[0]), "+f"(c[1]), "+f"(c[2]), "+f"(c[3])
        : "r"(a[0]), "r"(a[1]), "r"(a[2]), "r"(a[3]), "r"(b[0]), "r"(b[1]));
}

__device__ __forceinline__ void cpa16(void* s, const void* g) {
    uint32_t sa = (uint32_t)__cvta_generic_to_shared(s);
    asm volatile("cp.async.cg.shared.global [%0], [%1], 16;\n" :: "r"(sa), "l"(g));
}

template<int BN, bool TRANSC>
__global__ void __launch_bounds__(256, 2)
gemm_tc_kernel(const float* __restrict__ A, const float* __restrict__ Bm,
               const float* __restrict__ bias, float* __restrict__ C,
               int K, int lda, int ldb, int ldc,
               long long aO, long long aI, long long bO, long long bI,
               long long cO, long long cI, int zdiv,
               int flags, float alpha) {
    constexpr int WM   = (BN == 128) ? 64 : 32;   // warp tile M
    constexpr int RW   = 128 / WM;                // warps along M
    constexpr int MI   = WM / 16;                 // m16 tiles per warp
    constexpr int BPAD = BN + 8;                  // == 8 (mod 32): conflict-free frags

    int z = blockIdx.z;
    int zo = z / zdiv, zi = z - zo * zdiv;
    A  += zo * aO + zi * aI;
    Bm += zo * bO + zi * bI;
    C  += zo * cO + zi * cI;
    int m0 = blockIdx.y * 128;
    int n0 = blockIdx.x * BN;

    __shared__ float As[2][128][APAD];
    __shared__ float Bs[2][16][BPAD];

    int tid = threadIdx.x;
    int lane = tid & 31, warp = tid >> 5;
    int wm = warp % RW, wn = warp / RW;
    int grp = lane >> 2, qid = lane & 3;

    float acc[MI][4][4];
    #pragma unroll
    for (int i = 0; i < MI; i++)
        #pragma unroll
        for (int j = 0; j < 4; j++)
            #pragma unroll
            for (int r = 0; r < 4; r++) acc[i][j][r] = 0.f;

    auto load_tile = [&](int st, int k0) {
        #pragma unroll
        for (int i = 0; i < 2; i++) {
            int fid = tid + i * 256;
            int m = fid >> 2, kq = (fid & 3) << 2;
            cpa16(&As[st][m][kq], A + (long long)(m0 + m) * lda + k0 + kq);
        }
        if (BN == 128) {
            #pragma unroll
            for (int i = 0; i < 2; i++) {
                int fid = tid + i * 256;
                int kk = fid >> 5, nq = (fid & 31) << 2;
                cpa16(&Bs[st][kk][nq], Bm + (long long)(k0 + kk) * ldb + n0 + nq);
            }
        } else {
            int kk = tid >> 4, nq = (tid & 15) << 2;
            cpa16(&Bs[st][kk][nq], Bm + (long long)(k0 + kk) * ldb + n0 + nq);
        }
    };

    load_tile(0, 0);
    asm volatile("cp.async.commit_group;\n");

    int s = 0;
    for (int k0 = 0; k0 < K; k0 += 16) {
        asm volatile("cp.async.wait_group 0;\n" ::: "memory");
        __syncthreads();                    // tile s visible; prev compute on s^1 done
        if (k0 + 16 < K) {
            load_tile(s ^ 1, k0 + 16);      // overlaps with compute below
            asm volatile("cp.async.commit_group;\n");
        }
        #pragma unroll
        for (int ks = 0; ks < 2; ks++) {
            int kk = ks * 8;
            uint32_t af[MI][4], bf[4][2];
            #pragma unroll
            for (int i = 0; i < MI; i++) {
                int am = wm * WM + i * 16 + grp;
                af[i][0] = f2tf(As[s][am    ][kk + qid]);
                af[i][1] = f2tf(As[s][am + 8][kk + qid]);
                af[i][2] = f2tf(As[s][am    ][kk + qid + 4]);
                af[i][3] = f2tf(As[s][am + 8][kk + qid + 4]);
            }
            #pragma unroll
            for (int j = 0; j < 4; j++) {
                int bn = wn * 32 + j * 8 + grp;
                bf[j][0] = f2tf(Bs[s][kk + qid    ][bn]);
                bf[j][1] = f2tf(Bs[s][kk + qid + 4][bn]);
            }
            #pragma unroll
            for (int i = 0; i < MI; i++)
                #pragma unroll
                for (int j = 0; j < 4; j++)
                    mma_tf32(acc[i][j], af[i], bf[j]);
        }
        s ^= 1;
    }

    // ---- epilogue
    bool accum = (flags & 2), doGelu = (flags & 4), hasBias = (flags & 8);
    #pragma unroll
    for (int i = 0; i < MI; i++) {
        #pragma unroll
        for (int j = 0; j < 4; j++) {
            int r0  = m0 + wm * WM + i * 16 + grp;
            int col = n0 + wn * 32 + j * 8 + qid * 2;
            if (TRANSC) {
                #pragma unroll
                for (int h = 0; h < 2; h++) {
                    int r = r0 + h * 8;
                    C[(long long)(col    ) * ldc + r] = acc[i][j][h * 2 + 0] * alpha;
                    C[(long long)(col + 1) * ldc + r] = acc[i][j][h * 2 + 1] * alpha;
                }
            } else {
                float bv0 = 0.f, bv1 = 0.f;
                if (hasBias) { bv0 = bias[col]; bv1 = bias[col + 1]; }
                #pragma unroll
                for (int h = 0; h < 2; h++) {
                    int r = r0 + h * 8;
                    float v0 = acc[i][j][h * 2 + 0] * alpha + bv0;
                    float v1 = acc[i][j][h * 2 + 1] * alpha + bv1;
                    if (doGelu) {
                        v0 = 0.5f * v0 * (1.0f + erff(v0 * 0.70710678118654752f));
                        v1 = 0.5f * v1 * (1.0f + erff(v1 * 0.70710678118654752f));
                    }
                    float* p = C + (long long)r * ldc + col;
                    if (accum) {
                        float2 old = *(float2*)p;
                        v0 += old.x; v1 += old.y;
                    }
                    *(float2*)p = make_float2(v0, v1);
                }
            }
        }
    }
}

// ---------------- attention softmax (col mask + row mask) ----------------
__global__ void attn_softmax_kernel(float* __restrict__ wei,
                                    const int* __restrict__ lengths) {
    int t = blockIdx.x, h = blockIdx.y, b = blockIdx.z;
    int len = lengths[b];
    float* row = wei + (((long long)(b * NH + h)) * NT + t) * NT;
    int tid = threadIdx.x;
    int s0 = tid * 4;
    if (t >= len) {
        *(float4*)(row + s0) = make_float4(0.f, 0.f, 0.f, 0.f);
        return;
    }
    __shared__ float red[32];
    float4 v = *(const float4*)(row + s0);
    float vals[4] = {v.x, v.y, v.z, v.w};
    float m = -3.0e38f;
    #pragma unroll
    for (int j = 0; j < 4; j++) if (s0 + j < len) m = fmaxf(m, vals[j]);
    m = blockReduceMax(m, red);
    float e[4]; float sum = 0.f;
    #pragma unroll
    for (int j = 0; j < 4; j++) {
        e[j] = (s0 + j < len) ? expf(vals[j] - m) : 0.f;
        sum += e[j];
    }
    sum = blockReduceSum(sum, red);
    float inv = 1.0f / sum;
    *(float4*)(row + s0) = make_float4(e[0]*inv, e[1]*inv, e[2]*inv, e[3]*inv);
}

// ---------------- pooling ----------------
__global__ void score_kernel(const float* __restrict__ xn,
                             const float* __restrict__ attn_w,
                             const float* __restrict__ attn_b,
                             float* __restrict__ scores) {
    __shared__ float red[32];
    int bt = blockIdx.x, tid = threadIdx.x;
    float4 xv = *(const float4*)(xn + (long long)bt * DM + tid * 4);
    float4 wv = *(const float4*)(attn_w + tid * 4);
    float s = xv.x*wv.x + xv.y*wv.y + xv.z*wv.z + xv.w*wv.w;
    s = blockReduceSum(s, red);
    if (tid == 0) scores[bt] = s + attn_b[0];
}

__global__ void pool_softmax_kernel(const float* __restrict__ scores,
                                    const int* __restrict__ lengths,
                                    float* __restrict__ aw) {
    __shared__ float red[32];
    int b = blockIdx.x, t = threadIdx.x;
    int len = lengths[b];
    float s = (t < len) ? scores[b * NT + t] : -3.0e38f;
    float m = blockReduceMax(s, red);
    float e = (t < len) ? expf(s - m) : 0.f;
    float sum = blockReduceSum(e, red);
    aw[b * NT + t] = e / sum;
}

__global__ void pool_sum_kernel(const float* __restrict__ xn,
                                const float* __restrict__ aw,
                                float* __restrict__ part) {
    int b = blockIdx.y, c = blockIdx.x, d = threadIdx.x;
    float acc = 0.f;
    int t0 = c * 128;
    for (int t = t0; t < t0 + 128; t++)
        acc += aw[b * NT + t] * xn[((long long)b * NT + t) * DM + d];
    part[(b * 8 + c) * DM + d] = acc;
}

__global__ void logits_kernel(const float* __restrict__ part,
                              const float* __restrict__ head_w,
                              const float* __restrict__ head_b,
                              float* __restrict__ out) {
    __shared__ float summ[DM];
    int b = blockIdx.x, o = threadIdx.x;
    for (int d = o; d < DM; d += 64) {
        float s = 0.f;
        for (int c = 0; c < 8; c++) s += part[(b * 8 + c) * DM + d];
        summ[d] = s;
    }
    __syncthreads();
    if (o < NO) {
        float acc = head_b[o];
        for (int d = 0; d < DM; d++) acc += summ[d] * head_w[d * NO + o];
        out[b * NO + o] = acc;
    }
}

// ---------------- host wrappers ----------------
static void gemm128(const float* A, const float* B, const float* bias, float* C,
                    int M, int N, int K, int lda, int ldb, int ldc,
                    long long aO, long long aI, long long bO, long long bI,
                    long long cO, long long cI, int zdiv, int z,
                    int flags, float alpha) {
    dim3 grid(N / 128, M / 128, z);
    gemm_tc_kernel<128, false><<<grid, 256>>>(A, B, bias, C, K, lda, ldb, ldc,
                                              aO, aI, bO, bI, cO, cI, zdiv, flags, alpha);
}
static void gemm64(const float* A, const float* B, const float* bias, float* C,
                   int M, int N, int K, int lda, int ldb, int ldc,
                   long long aO, long long aI, long long bO, long long bI,
                   long long cO, long long cI, int zdiv, int z,
                   int flags, float alpha) {
    dim3 grid(N / 64, M / 128, z);
    gemm_tc_kernel<64, false><<<grid, 256>>>(A, B, bias, C, K, lda, ldb, ldc,
                                             aO, aI, bO, bI, cO, cI, zdiv, flags, alpha);
}
static void gemm64T(const float* A, const float* B, float* C,
                    int M, int N, int K, int lda, int ldb, int ldc,
                    long long aO, long long aI, long long bO, long long bI,
                    long long cO, long long cI, int zdiv, int z, float alpha) {
    dim3 grid(N / 64, M / 128, z);
    gemm_tc_kernel<64, true><<<grid, 256>>>(A, B, nullptr, C, K, lda, ldb, ldc,
                                            aO, aI, bO, bI, cO, cI, zdiv, 0, alpha);
}

extern "C" void kernel_launch(void* const* d_in, const int* in_sizes, int n_in,
                              void* d_out, int out_size) {
    const int*   code    = (const int*)  d_in[0];
    const int*   lengths = (const int*)  d_in[1];
    const float* emb     = (const float*)d_in[2];
    const float* Wq      = (const float*)d_in[3];
    const float* Wk      = (const float*)d_in[4];
    const float* Wv      = (const float*)d_in[5];
    const float* Wo      = (const float*)d_in[6];
    const float* bo      = (const float*)d_in[7];
    const float* W1      = (const float*)d_in[8];
    const float* b1      = (const float*)d_in[9];
    const float* W2      = (const float*)d_in[10];
    const float* b2      = (const float*)d_in[11];
    const float* ln1_g   = (const float*)d_in[12];
    const float* ln1_b   = (const float*)d_in[13];
    const float* ln2_g   = (const float*)d_in[14];
    const float* ln2_b   = (const float*)d_in[15];
    const float* lnf_g   = (const float*)d_in[16];
    const float* lnf_b   = (const float*)d_in[17];
    const float* attn_w  = (const float*)d_in[18];
    const float* attn_b  = (const float*)d_in[19];
    const float* head_w  = (const float*)d_in[20];
    const float* head_b  = (const float*)d_in[21];
    float* out = (float*)d_out;

    float *x, *xn, *q, *kT, *v, *o, *h1, *wei, *scr, *aw, *part, *Wrep;
    cudaGetSymbolAddress((void**)&x,   g_x);
    cudaGetSymbolAddress((void**)&xn,  g_xn);
    cudaGetSymbolAddress((void**)&q,   g_q);
    cudaGetSymbolAddress((void**)&kT,  g_k);
    cudaGetSymbolAddress((void**)&v,   g_v);
    cudaGetSymbolAddress((void**)&o,   g_o);
    cudaGetSymbolAddress((void**)&h1,  g_h1);
    cudaGetSymbolAddress((void**)&wei, g_wei);
    cudaGetSymbolAddress((void**)&scr, g_scores);
    cudaGetSymbolAddress((void**)&aw,  g_aw);
    cudaGetSymbolAddress((void**)&part,g_part);
    cudaGetSymbolAddress((void**)&Wrep,g_Wrep);

    const long long sBH  = (long long)NT * DM;     // 524288: per-batch rows stride
    const long long sTT  = (long long)NT * NT;     // per-head stride in wei
    const long long sKTb = (long long)NH * DHS * NT; // 524288: per-batch in kT
    const long long sKTh = (long long)DHS * NT;      // 65536: per-head in kT
    const long long sWl  = (long long)DM * DM;       // 262144: per-layer repacked W

    // repack Wq/Wk/Wv -> [w][l][d][h*64+e]
    repack_kernel<<<dim3(NL * DM * DM / 256, 3), 256>>>(Wq, Wk, Wv, Wrep);

    embed_kernel<<<BT, 128>>>(code, emb, x);

    for (int l = 0; l < NL; l++) {
        const float* Wrq = Wrep + (long long)0 * NL * sWl + l * sWl;
        const float* Wrk = Wrep + (long long)1 * NL * sWl + l * sWl;
        const float* Wrv = Wrep + (long long)2 * NL * sWl + l * sWl;
        const float* Wol = Wo + (long long)l * DM * DM;
        const float* W1l = W1 + (long long)l * DM * DFF;
        const float* W2l = W2 + (long long)l * DFF * DM;

        ln_kernel<<<BT, 128>>>(x, ln1_g + l * DM, ln1_b + l * DM, xn);

        // q = xn @ Wrq   (single big GEMM, all heads)
        gemm128(xn, Wrq, nullptr, q, BT, DM, DM, DM, DM, DM,
                0, 0, 0, 0, 0, 0, 1, 1, 0, 1.0f);
        // v = xn @ Wrv
        gemm128(xn, Wrv, nullptr, v, BT, DM, DM, DM, DM, DM,
                0, 0, 0, 0, 0, 0, 1, 1, 0, 1.0f);
        // kT[b][h][e][t] = (xn_b @ Wrk[:,h*64:...])^T  — z=64 over (b,h), transC
        gemm64T(xn, Wrk, kT, NT, DHS, DM, DM, DM, NT,
                sBH, 0, 0, DHS, sKTb, sKTh, 8, NB * NH, 1.0f);

        // wei = 0.125 * q @ kT, z=64 over (b,h)
        gemm128(q, kT, nullptr, wei, NT, NT, DHS, DM, NT, NT,
                sBH, DHS, sKTb, sKTh, (long long)NH * sTT, sTT, 8, NB * NH,
                0, 0.125f);

        attn_softmax_kernel<<<dim3(NT, NH, NB), 256>>>(wei, lengths);

        // o = wei @ v, z=64 over (b,h)
        gemm64(wei, v, nullptr, o, NT, DHS, NT, NT, DM, DM,
               (long long)NH * sTT, sTT, sBH, DHS, sBH, DHS, 8, NB * NH, 0, 1.0f);

        // x += o @ Wo + bo
        gemm128(o, Wol, bo + l * DM, x, BT, DM, DM, DM, DM, DM,
                0, 0, 0, 0, 0, 0, 1, 1, 2 | 8, 1.0f);

        ln_kernel<<<BT, 128>>>(x, ln2_g + l * DM, ln2_b + l * DM, xn);

        // h1 = gelu(xn @ W1 + b1)
        gemm128(xn, W1l, b1 + l * DFF, h1, BT, DFF, DM, DM, DFF, DFF,
                0, 0, 0, 0, 0, 0, 1, 1, 4 | 8, 1.0f);

        // x += h1 @ W2 + b2
        gemm128(h1, W2l, b2 + l * DM, x, BT, DM, DFF, DFF, DM, DM,
                0, 0, 0, 0, 0, 0, 1, 1, 2 | 8, 1.0f);
    }

    ln_kernel<<<BT, 128>>>(x, lnf_g, lnf_b, xn);
    score_kernel<<<BT, 128>>>(xn, attn_w, attn_b, scr);
    pool_softmax_kernel<<<NB, 1024>>>(scr, lengths, aw);
    pool_sum_kernel<<<dim3(8, NB), 512>>>(xn, aw, part);
    logits_kernel<<<NB, 64>>>(part, head_w, head_b, out);
}

// round 7
// speedup vs baseline: 3.1138x; 1.2387x over previous
#include <cuda_runtime.h>
#include <math.h>
#include <stdint.h>

#define NL 6
#define NH 8
#define DM 512
#define DHS 64
#define NB 8
#define NT 1024
#define NF 32
#define NE 16
#define DFF 2048
#define NO 49
#define BT (NB*NT)
#define EPSV 1e-5f

// ---------------- scratch (device globals: no allocation allowed) ----------
__device__ float g_x [BT*DM];
__device__ float g_xn[BT*DM];
__device__ float g_q [BT*DM];
__device__ float g_k [BT*DM];      // used as kT[b][h][e][t]
__device__ float g_v [BT*DM];
__device__ float g_o [BT*DM];
__device__ float g_h1[BT*DFF];
__device__ float g_wei[NB*NH*NT*NT];       // 256 MB attention scores
__device__ float g_scores[BT];
__device__ float g_aw[BT];
__device__ float g_part[NB*8*DM];
__device__ float g_Wrep[3*NL*DM*DM];       // repacked+rounded Wq/Wk/Wv
__device__ float g_WoR [NL*DM*DM];         // rounded Wo
__device__ float g_W1R [NL*DM*DFF];        // rounded W1
__device__ float g_W2R [NL*DFF*DM];        // rounded W2

// ---------------- tf32 helpers ----------------
__device__ __forceinline__ uint32_t f2tf(float x) {
    uint32_t r;
    asm("cvt.rna.tf32.f32 %0, %1;" : "=r"(r) : "f"(x));
    return r;
}
__device__ __forceinline__ float tff(float x) { return __uint_as_float(f2tf(x)); }

// ---------------- reductions ----------------
__device__ __forceinline__ float blockReduceSum(float v, float* sbuf) {
    int lane = threadIdx.x & 31, wid = threadIdx.x >> 5;
    #pragma unroll
    for (int o = 16; o > 0; o >>= 1) v += __shfl_down_sync(0xffffffffu, v, o);
    if (lane == 0) sbuf[wid] = v;
    __syncthreads();
    int nw = blockDim.x >> 5;
    v = (threadIdx.x < nw) ? sbuf[threadIdx.x] : 0.f;
    if (wid == 0) {
        #pragma unroll
        for (int o = 16; o > 0; o >>= 1) v += __shfl_down_sync(0xffffffffu, v, o);
        if (lane == 0) sbuf[0] = v;
    }
    __syncthreads();
    float r = sbuf[0];
    __syncthreads();
    return r;
}

__device__ __forceinline__ float blockReduceMax(float v, float* sbuf) {
    int lane = threadIdx.x & 31, wid = threadIdx.x >> 5;
    #pragma unroll
    for (int o = 16; o > 0; o >>= 1) v = fmaxf(v, __shfl_down_sync(0xffffffffu, v, o));
    if (lane == 0) sbuf[wid] = v;
    __syncthreads();
    int nw = blockDim.x >> 5;
    v = (threadIdx.x < nw) ? sbuf[threadIdx.x] : -3.0e38f;
    if (wid == 0) {
        #pragma unroll
        for (int o = 16; o > 0; o >>= 1) v = fmaxf(v, __shfl_down_sync(0xffffffffu, v, o));
        if (lane == 0) sbuf[0] = v;
    }
    __syncthreads();
    float r = sbuf[0];
    __syncthreads();
    return r;
}

// ---------------- weight repack (with tf32 rounding) ----------------
// out[w][l][d][h*64+e] = round(W_w[l][h][d][e])
__global__ void repack_kernel(const float* __restrict__ Wq,
                              const float* __restrict__ Wk,
                              const float* __restrict__ Wv,
                              float* __restrict__ out) {
    int idx = blockIdx.x * 256 + threadIdx.x;
    int w = blockIdx.y;
    int n = idx & 511;
    int h = n >> 6, e = n & 63;
    int ld = idx >> 9;
    int d = ld & 511, l = ld >> 9;
    const float* W = (w == 0) ? Wq : (w == 1) ? Wk : Wv;
    out[(long long)w * NL * DM * DM + idx] =
        tff(W[(((long long)(l * NH + h)) * DM + d) * DHS + e]);
}

__global__ void roundcopy_kernel(const float* __restrict__ in,
                                 float* __restrict__ out, int n4) {
    int i = blockIdx.x * 256 + threadIdx.x;
    if (i < n4) {
        float4 v = ((const float4*)in)[i];
        v.x = tff(v.x); v.y = tff(v.y); v.z = tff(v.z); v.w = tff(v.w);
        ((float4*)out)[i] = v;
    }
}

// ---------------- embed + posenc ----------------
__global__ void embed_kernel(const int* __restrict__ code,
                             const float* __restrict__ emb,
                             float* __restrict__ x) {
    int bt = blockIdx.x;
    int t  = bt & (NT - 1);
    int d0 = threadIdx.x * 4;
    const int* crow = code + (long long)bt * NF;
    float4 out;
    float* po = (float*)&out;
    #pragma unroll
    for (int j = 0; j < 4; j++) {
        int d = d0 + j;
        int f = d >> 4, e = d & 15;
        int c = crow[f];
        float df  = expf(-(float)(d & ~1) * (9.210340371976184f / 512.0f));
        float ang = (float)t * df;
        float pe  = (d & 1) ? cosf(ang) : sinf(ang);
        po[j] = emb[c * NE + e] + pe;
    }
    *(float4*)(x + (long long)bt * DM + d0) = out;
}

// ---------------- layernorm (optional tf32-rounded output) ----------------
__global__ void ln_kernel(const float* __restrict__ in,
                          const float* __restrict__ g,
                          const float* __restrict__ b,
                          float* __restrict__ out, int rnd) {
    __shared__ float red[32];
    int bt = blockIdx.x;
    int tid = threadIdx.x;
    float4 v = *(const float4*)(in + (long long)bt * DM + tid * 4);
    float s = v.x + v.y + v.z + v.w;
    s = blockReduceSum(s, red);
    float mean = s * (1.0f / DM);
    float d0 = v.x - mean, d1 = v.y - mean, d2 = v.z - mean, d3 = v.w - mean;
    float s2 = d0*d0 + d1*d1 + d2*d2 + d3*d3;
    s2 = blockReduceSum(s2, red);
    float inv = rsqrtf(s2 * (1.0f / DM) + EPSV);
    float4 gg = *(const float4*)(g + tid * 4);
    float4 bb = *(const float4*)(b + tid * 4);
    float4 o;
    o.x = d0 * inv * gg.x + bb.x;
    o.y = d1 * inv * gg.y + bb.y;
    o.z = d2 * inv * gg.z + bb.z;
    o.w = d3 * inv * gg.w + bb.w;
    if (rnd) { o.x = tff(o.x); o.y = tff(o.y); o.z = tff(o.z); o.w = tff(o.w); }
    *(float4*)(out + (long long)bt * DM + tid * 4) = o;
}

// ---------------- TF32 tensor-core batched GEMM ----------------
// 3-stage cp.async pipeline, BK=32, BM=128, BN template (64/128).
// Inputs must already be tf32-rounded (round-at-producer).
// flags: 2=accumulate, 4=gelu, 8=bias, 16=round output to tf32.
// TRANSC: C[col*ldc + row] = round(acc*alpha).
#define AP 36

__device__ __forceinline__ void mma_tf32(float c[4], const uint32_t a[4], const uint32_t b[2]) {
    asm volatile(
        "mma.sync.aligned.m16n8k8.row.col.f32.tf32.tf32.f32 "
        "{%0,%1,%2,%3}, {%4,%5,%6,%7}, {%8,%9}, {%0,%1,%2,%3};"
        : "+f"(c[0]), "+f"(c[1]), "+f"(c[2]), "+f"(c[3])
        : "r"(a[0]), "r"(a[1]), "r"(a[2]), "r"(a[3]), "r"(b[0]), "r"(b[1]));
}

__device__ __forceinline__ void cpa16(uint32_t s, const void* g) {
    asm volatile("cp.async.cg.shared.global [%0], [%1], 16;\n" :: "r"(s), "l"(g));
}
__device__ __forceinline__ void cpcommit() {
    asm volatile("cp.async.commit_group;\n" ::: "memory");
}

template<int BN, bool TRANSC>
__global__ void __launch_bounds__(256, 2)
gemm_tc_kernel(const float* __restrict__ A, const float* __restrict__ Bm,
               const float* __restrict__ bias, float* __restrict__ C,
               int K, int lda, int ldb, int ldc,
               long long aO, long long aI, long long bO, long long bI,
               long long cO, long long cI, int zdiv,
               int flags, float alpha) {
    constexpr int WM   = (BN == 128) ? 64 : 32;
    constexpr int RW   = 128 / WM;
    constexpr int MI   = WM / 16;
    constexpr int BP   = BN + 8;
    constexpr int NBLD = (BN == 128) ? 4 : 2;
    constexpr int BSTP = (BN == 128) ? 8 : 16;     // k-rows per B load chunk

    extern __shared__ float smem[];
    float* Asm = smem;                    // 3 stages of 128 x AP
    float* Bsm = smem + 3 * 128 * AP;     // 3 stages of 32 x BP

    int z = blockIdx.z;
    int zo = z / zdiv, zi = z - zo * zdiv;
    A  += zo * aO + zi * aI;
    Bm += zo * bO + zi * bI;
    C  += zo * cO + zi * cI;
    int m0 = blockIdx.y * 128;
    int n0 = blockIdx.x * BN;

    int tid = threadIdx.x, lane = tid & 31, warp = tid >> 5;
    int wm = warp % RW, wn = warp / RW;
    int grp = lane >> 2, qid = lane & 3;

    // ---- per-thread precomputed load geometry (all int offsets)
    int am_ = tid >> 3;                 // 0..31
    int ak_ = (tid & 7) << 2;           // 0..28
    const float* gA = A + (long long)(m0 + am_) * lda + ak_;
    uint32_t dAoff[4]; int aG[4];
    #pragma unroll
    for (int i = 0; i < 4; i++) {
        dAoff[i] = (uint32_t)(((am_ + 32 * i) * AP + ak_) * 4);
        aG[i] = 32 * i * lda;
    }
    int bk_ = (BN == 128) ? (tid >> 5) : (tid >> 4);
    int bn_ = (BN == 128) ? ((tid & 31) << 2) : ((tid & 15) << 2);
    const float* gB = Bm + (long long)bk_ * ldb + n0 + bn_;
    uint32_t dBoff[NBLD]; int bG[NBLD];
    #pragma unroll
    for (int i = 0; i < NBLD; i++) {
        dBoff[i] = (uint32_t)(((bk_ + BSTP * i) * BP + bn_) * 4);
        bG[i] = BSTP * i * ldb;
    }

    uint32_t smA = (uint32_t)__cvta_generic_to_shared(Asm);
    uint32_t smB = (uint32_t)__cvta_generic_to_shared(Bsm);
    constexpr uint32_t SZA = 128 * AP * 4;
    constexpr uint32_t SZB = 32 * BP * 4;

    auto load_tile = [&](int st, int k0) {
        uint32_t bA = smA + st * SZA;
        uint32_t bB = smB + st * SZB;
        #pragma unroll
        for (int i = 0; i < 4; i++)
            cpa16(bA + dAoff[i], gA + k0 + aG[i]);
        int bko = k0 * ldb;
        #pragma unroll
        for (int i = 0; i < NBLD; i++)
            cpa16(bB + dBoff[i], gB + bko + bG[i]);
    };

    float acc[MI][4][4];
    #pragma unroll
    for (int i = 0; i < MI; i++)
        #pragma unroll
        for (int j = 0; j < 4; j++)
            #pragma unroll
            for (int r = 0; r < 4; r++) acc[i][j][r] = 0.f;

    load_tile(0, 0);  cpcommit();
    load_tile(1, 32); cpcommit();          // K >= 64 always holds here

    int aoff = (wm * WM + grp) * AP + qid;
    int boff = qid * BP + wn * 32 + grp;

    int s = 0;
    for (int k0 = 0; k0 < K; k0 += 32) {
        asm volatile("cp.async.wait_group 1;\n" ::: "memory");
        __syncthreads();
        if (k0 + 64 < K) {
            int s2 = (s + 2) % 3;
            load_tile(s2, k0 + 64);
        }
        cpcommit();                        // always commit (possibly empty group)

        const uint32_t* uA = (const uint32_t*)(Asm + s * 128 * AP) + aoff;
        const uint32_t* uB = (const uint32_t*)(Bsm + s * 32 * BP) + boff;
        #pragma unroll
        for (int ks = 0; ks < 4; ks++) {
            int kk = ks * 8;
            uint32_t af[MI][4], bf[4][2];
            #pragma unroll
            for (int i = 0; i < MI; i++) {
                af[i][0] = uA[(i * 16    ) * AP + kk    ];
                af[i][1] = uA[(i * 16 + 8) * AP + kk    ];
                af[i][2] = uA[(i * 16    ) * AP + kk + 4];
                af[i][3] = uA[(i * 16 + 8) * AP + kk + 4];
            }
            #pragma unroll
            for (int j = 0; j < 4; j++) {
                bf[j][0] = uB[ kk      * BP + j * 8];
                bf[j][1] = uB[(kk + 4) * BP + j * 8];
            }
            #pragma unroll
            for (int i = 0; i < MI; i++)
                #pragma unroll
                for (int j = 0; j < 4; j++)
                    mma_tf32(acc[i][j], af[i], bf[j]);
        }
        s = (s == 2) ? 0 : s + 1;
    }

    // ---- epilogue
    bool accum = (flags & 2), doGelu = (flags & 4), hasBias = (flags & 8), rnd = (flags & 16);
    #pragma unroll
    for (int i = 0; i < MI; i++) {
        #pragma unroll
        for (int j = 0; j < 4; j++) {
            int r0  = m0 + wm * WM + i * 16 + grp;
            int col = n0 + wn * 32 + j * 8 + qid * 2;
            if (TRANSC) {
                #pragma unroll
                for (int h = 0; h < 2; h++) {
                    int r = r0 + h * 8;
                    C[(long long)(col    ) * ldc + r] = tff(acc[i][j][h * 2 + 0] * alpha);
                    C[(long long)(col + 1) * ldc + r] = tff(acc[i][j][h * 2 + 1] * alpha);
                }
            } else {
                float bv0 = 0.f, bv1 = 0.f;
                if (hasBias) { bv0 = bias[col]; bv1 = bias[col + 1]; }
                #pragma unroll
                for (int h = 0; h < 2; h++) {
                    int r = r0 + h * 8;
                    float v0 = acc[i][j][h * 2 + 0] * alpha + bv0;
                    float v1 = acc[i][j][h * 2 + 1] * alpha + bv1;
                    if (doGelu) {
                        v0 = 0.5f * v0 * (1.0f + erff(v0 * 0.70710678118654752f));
                        v1 = 0.5f * v1 * (1.0f + erff(v1 * 0.70710678118654752f));
                    }
                    if (rnd) { v0 = tff(v0); v1 = tff(v1); }
                    float* p = C + (long long)r * ldc + col;
                    if (accum) {
                        float2 old = *(float2*)p;
                        v0 += old.x; v1 += old.y;
                    }
                    *(float2*)p = make_float2(v0, v1);
                }
            }
        }
    }
}

// ---------------- attention softmax (rounded probs out) ----------------
__global__ void attn_softmax_kernel(float* __restrict__ wei,
                                    const int* __restrict__ lengths) {
    int t = blockIdx.x, h = blockIdx.y, b = blockIdx.z;
    int len = lengths[b];
    float* row = wei + (((long long)(b * NH + h)) * NT + t) * NT;
    int tid = threadIdx.x;
    int s0 = tid * 4;
    if (t >= len) {
        *(float4*)(row + s0) = make_float4(0.f, 0.f, 0.f, 0.f);
        return;
    }
    __shared__ float red[32];
    float4 v = *(const float4*)(row + s0);
    float vals[4] = {v.x, v.y, v.z, v.w};
    float m = -3.0e38f;
    #pragma unroll
    for (int j = 0; j < 4; j++) if (s0 + j < len) m = fmaxf(m, vals[j]);
    m = blockReduceMax(m, red);
    float e[4]; float sum = 0.f;
    #pragma unroll
    for (int j = 0; j < 4; j++) {
        e[j] = (s0 + j < len) ? expf(vals[j] - m) : 0.f;
        sum += e[j];
    }
    sum = blockReduceSum(sum, red);
    float inv = 1.0f / sum;
    *(float4*)(row + s0) = make_float4(tff(e[0]*inv), tff(e[1]*inv),
                                       tff(e[2]*inv), tff(e[3]*inv));
}

// ---------------- pooling ----------------
__global__ void score_kernel(const float* __restrict__ xn,
                             const float* __restrict__ attn_w,
                             const float* __restrict__ attn_b,
                             float* __restrict__ scores) {
    __shared__ float red[32];
    int bt = blockIdx.x, tid = threadIdx.x;
    float4 xv = *(const float4*)(xn + (long long)bt * DM + tid * 4);
    float4 wv = *(const float4*)(attn_w + tid * 4);
    float s = xv.x*wv.x + xv.y*wv.y + xv.z*wv.z + xv.w*wv.w;
    s = blockReduceSum(s, red);
    if (tid == 0) scores[bt] = s + attn_b[0];
}

__global__ void pool_softmax_kernel(const float* __restrict__ scores,
                                    const int* __restrict__ lengths,
                                    float* __restrict__ aw) {
    __shared__ float red[32];
    int b = blockIdx.x, t = threadIdx.x;
    int len = lengths[b];
    float s = (t < len) ? scores[b * NT + t] : -3.0e38f;
    float m = blockReduceMax(s, red);
    float e = (t < len) ? expf(s - m) : 0.f;
    float sum = blockReduceSum(e, red);
    aw[b * NT + t] = e / sum;
}

__global__ void pool_sum_kernel(const float* __restrict__ xn,
                                const float* __restrict__ aw,
                                float* __restrict__ part) {
    int b = blockIdx.y, c = blockIdx.x, d = threadIdx.x;
    float acc = 0.f;
    int t0 = c * 128;
    for (int t = t0; t < t0 + 128; t++)
        acc += aw[b * NT + t] * xn[((long long)b * NT + t) * DM + d];
    part[(b * 8 + c) * DM + d] = acc;
}

__global__ void logits_kernel(const float* __restrict__ part,
                              const float* __restrict__ head_w,
                              const float* __restrict__ head_b,
                              float* __restrict__ out) {
    __shared__ float summ[DM];
    int b = blockIdx.x, o = threadIdx.x;
    for (int d = o; d < DM; d += 64) {
        float s = 0.f;
        for (int c = 0; c < 8; c++) s += part[(b * 8 + c) * DM + d];
        summ[d] = s;
    }
    __syncthreads();
    if (o < NO) {
        float acc = head_b[o];
        for (int d = 0; d < DM; d++) acc += summ[d] * head_w[d * NO + o];
        out[b * NO + o] = acc;
    }
}

// ---------------- host wrappers ----------------
#define SMEM128 ((3*128*AP + 3*32*(128+8)) * 4)   // 107520
#define SMEM64  ((3*128*AP + 3*32*(64+8))  * 4)   // 82944

static void gemm128(const float* A, const float* B, const float* bias, float* C,
                    int M, int N, int K, int lda, int ldb, int ldc,
                    long long aO, long long aI, long long bO, long long bI,
                    long long cO, long long cI, int zdiv, int z,
                    int flags, float alpha) {
    dim3 grid(N / 128, M / 128, z);
    gemm_tc_kernel<128, false><<<grid, 256, SMEM128>>>(A, B, bias, C, K, lda, ldb, ldc,
                                                       aO, aI, bO, bI, cO, cI, zdiv, flags, alpha);
}
static void gemm64(const float* A, const float* B, const float* bias, float* C,
                   int M, int N, int K, int lda, int ldb, int ldc,
                   long long aO, long long aI, long long bO, long long bI,
                   long long cO, long long cI, int zdiv, int z,
                   int flags, float alpha) {
    dim3 grid(N / 64, M / 128, z);
    gemm_tc_kernel<64, false><<<grid, 256, SMEM64>>>(A, B, bias, C, K, lda, ldb, ldc,
                                                     aO, aI, bO, bI, cO, cI, zdiv, flags, alpha);
}
static void gemm64T(const float* A, const float* B, float* C,
                    int M, int N, int K, int lda, int ldb, int ldc,
                    long long aO, long long aI, long long bO, long long bI,
                    long long cO, long long cI, int zdiv, int z, float alpha) {
    dim3 grid(N / 64, M / 128, z);
    gemm_tc_kernel<64, true><<<grid, 256, SMEM64>>>(A, B, nullptr, C, K, lda, ldb, ldc,
                                                    aO, aI, bO, bI, cO, cI, zdiv, 0, alpha);
}

extern "C" void kernel_launch(void* const* d_in, const int* in_sizes, int n_in,
                              void* d_out, int out_size) {
    const int*   code    = (const int*)  d_in[0];
    const int*   lengths = (const int*)  d_in[1];
    const float* emb     = (const float*)d_in[2];
    const float* Wq      = (const float*)d_in[3];
    const float* Wk      = (const float*)d_in[4];
    const float* Wv      = (const float*)d_in[5];
    const float* Wo      = (const float*)d_in[6];
    const float* bo      = (const float*)d_in[7];
    const float* W1      = (const float*)d_in[8];
    const float* b1      = (const float*)d_in[9];
    const float* W2      = (const float*)d_in[10];
    const float* b2      = (const float*)d_in[11];
    const float* ln1_g   = (const float*)d_in[12];
    const float* ln1_b   = (const float*)d_in[13];
    const float* ln2_g   = (const float*)d_in[14];
    const float* ln2_b   = (const float*)d_in[15];
    const float* lnf_g   = (const float*)d_in[16];
    const float* lnf_b   = (const float*)d_in[17];
    const float* attn_w  = (const float*)d_in[18];
    const float* attn_b  = (const float*)d_in[19];
    const float* head_w  = (const float*)d_in[20];
    const float* head_b  = (const float*)d_in[21];
    float* out = (float*)d_out;

    static int smem_set = 0;
    if (!smem_set) {
        cudaFuncSetAttribute(gemm_tc_kernel<128, false>,
                             cudaFuncAttributeMaxDynamicSharedMemorySize, SMEM128);
        cudaFuncSetAttribute(gemm_tc_kernel<64, false>,
                             cudaFuncAttributeMaxDynamicSharedMemorySize, SMEM64);
        cudaFuncSetAttribute(gemm_tc_kernel<64, true>,
                             cudaFuncAttributeMaxDynamicSharedMemorySize, SMEM64);
        smem_set = 1;
    }

    float *x, *xn, *q, *kT, *v, *o, *h1, *wei, *scr, *aw, *part;
    float *Wrep, *WoR, *W1R, *W2R;
    cudaGetSymbolAddress((void**)&x,   g_x);
    cudaGetSymbolAddress((void**)&xn,  g_xn);
    cudaGetSymbolAddress((void**)&q,   g_q);
    cudaGetSymbolAddress((void**)&kT,  g_k);
    cudaGetSymbolAddress((void**)&v,   g_v);
    cudaGetSymbolAddress((void**)&o,   g_o);
    cudaGetSymbolAddress((void**)&h1,  g_h1);
    cudaGetSymbolAddress((void**)&wei, g_wei);
    cudaGetSymbolAddress((void**)&scr, g_scores);
    cudaGetSymbolAddress((void**)&aw,  g_aw);
    cudaGetSymbolAddress((void**)&part,g_part);
    cudaGetSymbolAddress((void**)&Wrep,g_Wrep);
    cudaGetSymbolAddress((void**)&WoR, g_WoR);
    cudaGetSymbolAddress((void**)&W1R, g_W1R);
    cudaGetSymbolAddress((void**)&W2R, g_W2R);

    const long long sBH  = (long long)NT * DM;
    const long long sTT  = (long long)NT * NT;
    const long long sKTb = (long long)NH * DHS * NT;
    const long long sKTh = (long long)DHS * NT;
    const long long sWl  = (long long)DM * DM;

    // repack + round all weights once per call
    repack_kernel<<<dim3(NL * DM * DM / 256, 3), 256>>>(Wq, Wk, Wv, Wrep);
    roundcopy_kernel<<<(NL*DM*DM/4 + 255)/256, 256>>>(Wo, WoR, NL*DM*DM/4);
    roundcopy_kernel<<<(NL*DM*DFF/4 + 255)/256, 256>>>(W1, W1R, NL*DM*DFF/4);
    roundcopy_kernel<<<(NL*DFF*DM/4 + 255)/256, 256>>>(W2, W2R, NL*DFF*DM/4);

    embed_kernel<<<BT, 128>>>(code, emb, x);

    for (int l = 0; l < NL; l++) {
        const float* Wrq = Wrep + (long long)0 * NL * sWl + l * sWl;
        const float* Wrk = Wrep + (long long)1 * NL * sWl + l * sWl;
        const float* Wrv = Wrep + (long long)2 * NL * sWl + l * sWl;
        const float* Wol = WoR + (long long)l * DM * DM;
        const float* W1l = W1R + (long long)l * DM * DFF;
        const float* W2l = W2R + (long long)l * DFF * DM;

        ln_kernel<<<BT, 128>>>(x, ln1_g + l * DM, ln1_b + l * DM, xn, 1);

        // q = round(xn @ Wrq), v = round(xn @ Wrv)
        gemm128(xn, Wrq, nullptr, q, BT, DM, DM, DM, DM, DM,
                0, 0, 0, 0, 0, 0, 1, 1, 16, 1.0f);
        gemm128(xn, Wrv, nullptr, v, BT, DM, DM, DM, DM, DM,
                0, 0, 0, 0, 0, 0, 1, 1, 16, 1.0f);
        // kT[b][h][e][t] = round((xn_b @ Wrk_h)^T), z=64 over (b,h)
        gemm64T(xn, Wrk, kT, NT, DHS, DM, DM, DM, NT,
                sBH, 0, 0, DHS, sKTb, sKTh, 8, NB * NH, 1.0f);

        // wei = 0.125 * q @ kT
        gemm128(q, kT, nullptr, wei, NT, NT, DHS, DM, NT, NT,
                sBH, DHS, sKTb, sKTh, (long long)NH * sTT, sTT, 8, NB * NH,
                0, 0.125f);

        attn_softmax_kernel<<<dim3(NT, NH, NB), 256>>>(wei, lengths);

        // o = round(wei @ v)
        gemm64(wei, v, nullptr, o, NT, DHS, NT, NT, DM, DM,
               (long long)NH * sTT, sTT, sBH, DHS, sBH, DHS, 8, NB * NH, 16, 1.0f);

        // x += o @ Wo + bo  (fp32 residual, no rounding)
        gemm128(o, Wol, bo + l * DM, x, BT, DM, DM, DM, DM, DM,
                0, 0, 0, 0, 0, 0, 1, 1, 2 | 8, 1.0f);

        ln_kernel<<<BT, 128>>>(x, ln2_g + l * DM, ln2_b + l * DM, xn, 1);

        // h1 = round(gelu(xn @ W1 + b1))
        gemm128(xn, W1l, b1 + l * DFF, h1, BT, DFF, DM, DM, DFF, DFF,
                0, 0, 0, 0, 0, 0, 1, 1, 4 | 8 | 16, 1.0f);

        // x += h1 @ W2 + b2
        gemm128(h1, W2l, b2 + l * DM, x, BT, DM, DFF, DFF, DM, DM,
                0, 0, 0, 0, 0, 0, 1, 1, 2 | 8, 1.0f);
    }

    ln_kernel<<<BT, 128>>>(x, lnf_g, lnf_b, xn, 0);
    score_kernel<<<BT, 128>>>(xn, attn_w, attn_b, scr);
    pool_softmax_kernel<<<NB, 1024>>>(scr, lengths, aw);
    pool_sum_kernel<<<dim3(8, NB), 512>>>(xn, aw, part);
    logits_kernel<<<NB, 64>>>(part, head_w, head_b, out);
}

// round 9
// speedup vs baseline: 3.8759x; 1.2448x over previous
#include <cuda_runtime.h>
#include <math.h>
#include <stdint.h>

#define NL 6
#define NH 8
#define DM 512
#define DHS 64
#define NB 8
#define NT 1024
#define NF 32
#define NE 16
#define DFF 2048
#define NO 49
#define BT (NB*NT)
#define EPSV 1e-5f

// ---------------- scratch (device globals: no allocation allowed) ----------
__device__ float g_x [BT*DM];
__device__ float g_xn[BT*DM];
__device__ float g_q [BT*DM];
__device__ float g_k [BT*DM];
__device__ float g_v [BT*DM];
__device__ float g_o [BT*DM];
__device__ float g_h1[BT*DFF];
__device__ float g_scores[BT];
__device__ float g_aw[BT];
__device__ float g_part[NB*8*DM];
__device__ float g_Wrep[3*NL*DM*DM];       // repacked+rounded Wq/Wk/Wv
__device__ float g_WoR [NL*DM*DM];         // rounded Wo
__device__ float g_W1R [NL*DM*DFF];        // rounded W1
__device__ float g_W2R [NL*DFF*DM];        // rounded W2

// ---------------- tf32 helpers ----------------
__device__ __forceinline__ uint32_t f2tf(float x) {
    uint32_t r;
    asm("cvt.rna.tf32.f32 %0, %1;" : "=r"(r) : "f"(x));
    return r;
}
__device__ __forceinline__ float tff(float x) { return __uint_as_float(f2tf(x)); }

__device__ __forceinline__ void mma_tf32(float c[4], const uint32_t a[4], const uint32_t b[2]) {
    asm volatile(
        "mma.sync.aligned.m16n8k8.row.col.f32.tf32.tf32.f32 "
        "{%0,%1,%2,%3}, {%4,%5,%6,%7}, {%8,%9}, {%0,%1,%2,%3};"
        : "+f"(c[0]), "+f"(c[1]), "+f"(c[2]), "+f"(c[3])
        : "r"(a[0]), "r"(a[1]), "r"(a[2]), "r"(a[3]), "r"(b[0]), "r"(b[1]));
}

__device__ __forceinline__ void cpa16(uint32_t s, const void* g) {
    asm volatile("cp.async.cg.shared.global [%0], [%1], 16;\n" :: "r"(s), "l"(g));
}
__device__ __forceinline__ void cpcommit() {
    asm volatile("cp.async.commit_group;\n" ::: "memory");
}

// ---------------- reductions ----------------
__device__ __forceinline__ float blockReduceSum(float v, float* sbuf) {
    int lane = threadIdx.x & 31, wid = threadIdx.x >> 5;
    #pragma unroll
    for (int o = 16; o > 0; o >>= 1) v += __shfl_down_sync(0xffffffffu, v, o);
    if (lane == 0) sbuf[wid] = v;
    __syncthreads();
    int nw = blockDim.x >> 5;
    v = (threadIdx.x < nw) ? sbuf[threadIdx.x] : 0.f;
    if (wid == 0) {
        #pragma unroll
        for (int o = 16; o > 0; o >>= 1) v += __shfl_down_sync(0xffffffffu, v, o);
        if (lane == 0) sbuf[0] = v;
    }
    __syncthreads();
    float r = sbuf[0];
    __syncthreads();
    return r;
}

__device__ __forceinline__ float blockReduceMax(float v, float* sbuf) {
    int lane = threadIdx.x & 31, wid = threadIdx.x >> 5;
    #pragma unroll
    for (int o = 16; o > 0; o >>= 1) v = fmaxf(v, __shfl_down_sync(0xffffffffu, v, o));
    if (lane == 0) sbuf[wid] = v;
    __syncthreads();
    int nw = blockDim.x >> 5;
    v = (threadIdx.x < nw) ? sbuf[threadIdx.x] : -3.0e38f;
    if (wid == 0) {
        #pragma unroll
        for (int o = 16; o > 0; o >>= 1) v = fmaxf(v, __shfl_down_sync(0xffffffffu, v, o));
        if (lane == 0) sbuf[0] = v;
    }
    __syncthreads();
    float r = sbuf[0];
    __syncthreads();
    return r;
}

// ---------------- weight repack (with tf32 rounding) ----------------
__global__ void repack_kernel(const float* __restrict__ Wq,
                              const float* __restrict__ Wk,
                              const float* __restrict__ Wv,
                              float* __restrict__ out) {
    int idx = blockIdx.x * 256 + threadIdx.x;
    int w = blockIdx.y;
    int n = idx & 511;
    int h = n >> 6, e = n & 63;
    int ld = idx >> 9;
    int d = ld & 511, l = ld >> 9;
    const float* W = (w == 0) ? Wq : (w == 1) ? Wk : Wv;
    out[(long long)w * NL * DM * DM + idx] =
        tff(W[(((long long)(l * NH + h)) * DM + d) * DHS + e]);
}

__global__ void roundcopy_kernel(const float* __restrict__ in,
                                 float* __restrict__ out, int n4) {
    int i = blockIdx.x * 256 + threadIdx.x;
    if (i < n4) {
        float4 v = ((const float4*)in)[i];
        v.x = tff(v.x); v.y = tff(v.y); v.z = tff(v.z); v.w = tff(v.w);
        ((float4*)out)[i] = v;
    }
}

// ---------------- embed + posenc ----------------
__global__ void embed_kernel(const int* __restrict__ code,
                             const float* __restrict__ emb,
                             float* __restrict__ x) {
    int bt = blockIdx.x;
    int t  = bt & (NT - 1);
    int d0 = threadIdx.x * 4;
    const int* crow = code + (long long)bt * NF;
    float4 out;
    float* po = (float*)&out;
    #pragma unroll
    for (int j = 0; j < 4; j++) {
        int d = d0 + j;
        int f = d >> 4, e = d & 15;
        int c = crow[f];
        float df  = expf(-(float)(d & ~1) * (9.210340371976184f / 512.0f));
        float ang = (float)t * df;
        float pe  = (d & 1) ? cosf(ang) : sinf(ang);
        po[j] = emb[c * NE + e] + pe;
    }
    *(float4*)(x + (long long)bt * DM + d0) = out;
}

// ---------------- layernorm (optional tf32-rounded output) ----------------
__global__ void ln_kernel(const float* __restrict__ in,
                          const float* __restrict__ g,
                          const float* __restrict__ b,
                          float* __restrict__ out, int rnd) {
    __shared__ float red[32];
    int bt = blockIdx.x;
    int tid = threadIdx.x;
    float4 v = *(const float4*)(in + (long long)bt * DM + tid * 4);
    float s = v.x + v.y + v.z + v.w;
    s = blockReduceSum(s, red);
    float mean = s * (1.0f / DM);
    float d0 = v.x - mean, d1 = v.y - mean, d2 = v.z - mean, d3 = v.w - mean;
    float s2 = d0*d0 + d1*d1 + d2*d2 + d3*d3;
    s2 = blockReduceSum(s2, red);
    float inv = rsqrtf(s2 * (1.0f / DM) + EPSV);
    float4 gg = *(const float4*)(g + tid * 4);
    float4 bb = *(const float4*)(b + tid * 4);
    float4 o;
    o.x = d0 * inv * gg.x + bb.x;
    o.y = d1 * inv * gg.y + bb.y;
    o.z = d2 * inv * gg.z + bb.z;
    o.w = d3 * inv * gg.w + bb.w;
    if (rnd) { o.x = tff(o.x); o.y = tff(o.y); o.z = tff(o.z); o.w = tff(o.w); }
    *(float4*)(out + (long long)bt * DM + tid * 4) = o;
}

// ---------------- TF32 tensor-core batched GEMM ----------------
#define AP 36

template<int BN, bool TRANSC>
__global__ void __launch_bounds__(256, 2)
gemm_tc_kernel(const float* __restrict__ A, const float* __restrict__ Bm,
               const float* __restrict__ bias, float* __restrict__ C,
               int K, int lda, int ldb, int ldc,
               long long aO, long long aI, long long bO, long long bI,
               long long cO, long long cI, int zdiv,
               int flags, float alpha) {
    constexpr int WM   = (BN == 128) ? 64 : 32;
    constexpr int RW   = 128 / WM;
    constexpr int MI   = WM / 16;
    constexpr int BP   = BN + 8;
    constexpr int NBLD = (BN == 128) ? 4 : 2;
    constexpr int BSTP = (BN == 128) ? 8 : 16;

    extern __shared__ float smem[];
    float* Asm = smem;
    float* Bsm = smem + 3 * 128 * AP;

    int z = blockIdx.z;
    int zo = z / zdiv, zi = z - zo * zdiv;
    A  += zo * aO + zi * aI;
    Bm += zo * bO + zi * bI;
    C  += zo * cO + zi * cI;
    int m0 = blockIdx.y * 128;
    int n0 = blockIdx.x * BN;

    int tid = threadIdx.x, lane = tid & 31, warp = tid >> 5;
    int wm = warp % RW, wn = warp / RW;
    int grp = lane >> 2, qid = lane & 3;

    int am_ = tid >> 3;
    int ak_ = (tid & 7) << 2;
    const float* gA = A + (long long)(m0 + am_) * lda + ak_;
    uint32_t dAoff[4]; int aG[4];
    #pragma unroll
    for (int i = 0; i < 4; i++) {
        dAoff[i] = (uint32_t)(((am_ + 32 * i) * AP + ak_) * 4);
        aG[i] = 32 * i * lda;
    }
    int bk_ = (BN == 128) ? (tid >> 5) : (tid >> 4);
    int bn_ = (BN == 128) ? ((tid & 31) << 2) : ((tid & 15) << 2);
    const float* gB = Bm + (long long)bk_ * ldb + n0 + bn_;
    uint32_t dBoff[NBLD]; int bG[NBLD];
    #pragma unroll
    for (int i = 0; i < NBLD; i++) {
        dBoff[i] = (uint32_t)(((bk_ + BSTP * i) * BP + bn_) * 4);
        bG[i] = BSTP * i * ldb;
    }

    uint32_t smA = (uint32_t)__cvta_generic_to_shared(Asm);
    uint32_t smB = (uint32_t)__cvta_generic_to_shared(Bsm);
    constexpr uint32_t SZA = 128 * AP * 4;
    constexpr uint32_t SZB = 32 * BP * 4;

    auto load_tile = [&](int st, int k0) {
        uint32_t bA = smA + st * SZA;
        uint32_t bB = smB + st * SZB;
        #pragma unroll
        for (int i = 0; i < 4; i++)
            cpa16(bA + dAoff[i], gA + k0 + aG[i]);
        int bko = k0 * ldb;
        #pragma unroll
        for (int i = 0; i < NBLD; i++)
            cpa16(bB + dBoff[i], gB + bko + bG[i]);
    };

    float acc[MI][4][4];
    #pragma unroll
    for (int i = 0; i < MI; i++)
        #pragma unroll
        for (int j = 0; j < 4; j++)
            #pragma unroll
            for (int r = 0; r < 4; r++) acc[i][j][r] = 0.f;

    load_tile(0, 0);  cpcommit();
    load_tile(1, 32); cpcommit();

    int aoff = (wm * WM + grp) * AP + qid;
    int boff = qid * BP + wn * 32 + grp;

    int s = 0;
    for (int k0 = 0; k0 < K; k0 += 32) {
        asm volatile("cp.async.wait_group 1;\n" ::: "memory");
        __syncthreads();
        if (k0 + 64 < K) {
            int s2 = (s + 2) % 3;
            load_tile(s2, k0 + 64);
        }
        cpcommit();

        const uint32_t* uA = (const uint32_t*)(Asm + s * 128 * AP) + aoff;
        const uint32_t* uB = (const uint32_t*)(Bsm + s * 32 * BP) + boff;
        #pragma unroll
        for (int ks = 0; ks < 4; ks++) {
            int kk = ks * 8;
            uint32_t af[MI][4], bf[4][2];
            #pragma unroll
            for (int i = 0; i < MI; i++) {
                af[i][0] = uA[(i * 16    ) * AP + kk    ];
                af[i][1] = uA[(i * 16 + 8) * AP + kk    ];
                af[i][2] = uA[(i * 16    ) * AP + kk + 4];
                af[i][3] = uA[(i * 16 + 8) * AP + kk + 4];
            }
            #pragma unroll
            for (int j = 0; j < 4; j++) {
                bf[j][0] = uB[ kk      * BP + j * 8];
                bf[j][1] = uB[(kk + 4) * BP + j * 8];
            }
            #pragma unroll
            for (int i = 0; i < MI; i++)
                #pragma unroll
                for (int j = 0; j < 4; j++)
                    mma_tf32(acc[i][j], af[i], bf[j]);
        }
        s = (s == 2) ? 0 : s + 1;
    }

    bool accum = (flags & 2), doGelu = (flags & 4), hasBias = (flags & 8), rnd = (flags & 16);
    #pragma unroll
    for (int i = 0; i < MI; i++) {
        #pragma unroll
        for (int j = 0; j < 4; j++) {
            int r0  = m0 + wm * WM + i * 16 + grp;
            int col = n0 + wn * 32 + j * 8 + qid * 2;
            if (TRANSC) {
                #pragma unroll
                for (int h = 0; h < 2; h++) {
                    int r = r0 + h * 8;
                    C[(long long)(col    ) * ldc + r] = tff(acc[i][j][h * 2 + 0] * alpha);
                    C[(long long)(col + 1) * ldc + r] = tff(acc[i][j][h * 2 + 1] * alpha);
                }
            } else {
                float bv0 = 0.f, bv1 = 0.f;
                if (hasBias) { bv0 = bias[col]; bv1 = bias[col + 1]; }
                #pragma unroll
                for (int h = 0; h < 2; h++) {
                    int r = r0 + h * 8;
                    float v0 = acc[i][j][h * 2 + 0] * alpha + bv0;
                    float v1 = acc[i][j][h * 2 + 1] * alpha + bv1;
                    if (doGelu) {
                        v0 = 0.5f * v0 * (1.0f + erff(v0 * 0.70710678118654752f));
                        v1 = 0.5f * v1 * (1.0f + erff(v1 * 0.70710678118654752f));
                    }
                    if (rnd) { v0 = tff(v0); v1 = tff(v1); }
                    float* p = C + (long long)r * ldc + col;
                    if (accum) {
                        float2 old = *(float2*)p;
                        v0 += old.x; v1 += old.y;
                    }
                    *(float2*)p = make_float2(v0, v1);
                }
            }
        }
    }
}

// ---------------- fused flash attention ----------------
// q,k,v,o layout: [b*NT + t][h*64 + e] (tf32-rounded inputs).
// Per CTA: one (b, h, 128-row q-tile). 8 warps, 16 q-rows each.
// Online softmax in registers; P staged through smem for the PV mma.
#define FQP 68   // pad ≡ 4 (mod 32): conflict-free for A-op / K-op access patterns
#define FVP 72   // pad ≡ 8 (mod 32): conflict-free for B-op [k][n] access
#define FA_SMEM ((128*FQP + 2*64*FQP + 2*64*FVP + 128*FQP) * 4)

__global__ void __launch_bounds__(256, 1)
flash_attn_kernel(const float* __restrict__ q, const float* __restrict__ k,
                  const float* __restrict__ v, const int* __restrict__ lengths,
                  float* __restrict__ o) {
    extern __shared__ float fsm[];
    float* Qs = fsm;                       // [128][FQP]
    float* Ks = Qs + 128 * FQP;            // [2][64][FQP]
    float* Vs = Ks + 2 * 64 * FQP;         // [2][64][FVP]
    float* Ps = Vs + 2 * 64 * FVP;         // [128][FQP]

    int b = blockIdx.z, h = blockIdx.y, qt = blockIdx.x;
    int len = lengths[b];
    int tid = threadIdx.x, lane = tid & 31, warp = tid >> 5;
    int grp = lane >> 2, qid = lane & 3;
    int w16 = warp * 16;

    const float* Qg = q + ((long long)(b * NT + qt * 128)) * DM + h * DHS;
    const float* Kg = k + ((long long)b * NT) * DM + h * DHS;
    const float* Vg = v + ((long long)b * NT) * DM + h * DHS;

    // Q tile: 128 rows x 64 floats = 2048 16B chunks
    #pragma unroll
    for (int i = 0; i < 8; i++) {
        int cid = i * 256 + tid;
        int r = cid >> 4, c = (cid & 15) << 2;
        cpa16((uint32_t)__cvta_generic_to_shared(&Qs[r * FQP + c]),
              Qg + (long long)r * DM + c);
    }
    auto loadKV = [&](int buf, int sb) {
        int s0 = sb * 64;
        #pragma unroll
        for (int i = 0; i < 4; i++) {
            int cid = i * 256 + tid;
            int ss = cid >> 4, c = (cid & 15) << 2;
            const float* kg = Kg + (long long)(s0 + ss) * DM + c;
            const float* vg = Vg + (long long)(s0 + ss) * DM + c;
            cpa16((uint32_t)__cvta_generic_to_shared(&Ks[(buf * 64 + ss) * FQP + c]), kg);
            cpa16((uint32_t)__cvta_generic_to_shared(&Vs[(buf * 64 + ss) * FVP + c]), vg);
        }
    };

    int nsb = (len + 63) >> 6;             // len >= 512 -> nsb >= 8
    loadKV(0, 0);
    cpcommit();

    float m_[2] = {-1e30f, -1e30f};
    float l_[2] = {0.f, 0.f};
    float oacc[8][4];
    #pragma unroll
    for (int j = 0; j < 8; j++) { oacc[j][0]=oacc[j][1]=oacc[j][2]=oacc[j][3]=0.f; }

    for (int sb = 0; sb < nsb; sb++) {
        asm volatile("cp.async.wait_group 0;\n" ::: "memory");
        __syncthreads();
        int buf = sb & 1;
        if (sb + 1 < nsb) { loadKV(buf ^ 1, sb + 1); cpcommit(); }

        // ---- S = Q @ K^T (warp rows w16..w16+15, all 64 s-cols)
        float sacc[8][4];
        #pragma unroll
        for (int j = 0; j < 8; j++) { sacc[j][0]=sacc[j][1]=sacc[j][2]=sacc[j][3]=0.f; }
        const uint32_t* uQ = (const uint32_t*)Qs;
        const uint32_t* uK = (const uint32_t*)(Ks + buf * 64 * FQP);
        #pragma unroll
        for (int ks = 0; ks < 8; ks++) {
            int kk = ks * 8;
            uint32_t af[4];
            af[0] = uQ[(w16 + grp    ) * FQP + kk + qid];
            af[1] = uQ[(w16 + grp + 8) * FQP + kk + qid];
            af[2] = uQ[(w16 + grp    ) * FQP + kk + qid + 4];
            af[3] = uQ[(w16 + grp + 8) * FQP + kk + qid + 4];
            #pragma unroll
            for (int j = 0; j < 8; j++) {
                uint32_t bf[2];
                bf[0] = uK[(j * 8 + grp) * FQP + kk + qid];
                bf[1] = uK[(j * 8 + grp) * FQP + kk + qid + 4];
                mma_tf32(sacc[j], af, bf);
            }
        }

        // ---- online softmax (rows grp / grp+8; cols spread over qid quad)
        int s0 = sb * 64;
        #pragma unroll
        for (int hh = 0; hh < 2; hh++) {
            float mx = -1e30f;
            #pragma unroll
            for (int j = 0; j < 8; j++) {
                #pragma unroll
                for (int c = 0; c < 2; c++) {
                    float val = sacc[j][hh * 2 + c] * 0.125f;
                    if (s0 + j * 8 + qid * 2 + c >= len) val = -1e30f;
                    sacc[j][hh * 2 + c] = val;
                    mx = fmaxf(mx, val);
                }
            }
            mx = fmaxf(mx, __shfl_xor_sync(0xffffffffu, mx, 1));
            mx = fmaxf(mx, __shfl_xor_sync(0xffffffffu, mx, 2));
            float mn = fmaxf(m_[hh], mx);
            float sc = __expf(m_[hh] - mn);
            float rs = 0.f;
            #pragma unroll
            for (int j = 0; j < 8; j++) {
                #pragma unroll
                for (int c = 0; c < 2; c++) {
                    float p = __expf(sacc[j][hh * 2 + c] - mn);
                    sacc[j][hh * 2 + c] = p;
                    rs += p;
                }
            }
            rs += __shfl_xor_sync(0xffffffffu, rs, 1);
            rs += __shfl_xor_sync(0xffffffffu, rs, 2);
            l_[hh] = l_[hh] * sc + rs;
            m_[hh] = mn;
            #pragma unroll
            for (int j = 0; j < 8; j++) {
                oacc[j][hh * 2 + 0] *= sc;
                oacc[j][hh * 2 + 1] *= sc;
            }
        }

        // ---- stage P (own warp rows only), then O += P @ V
        #pragma unroll
        for (int j = 0; j < 8; j++) {
            *(float2*)&Ps[(w16 + grp    ) * FQP + j * 8 + qid * 2] =
                make_float2(tff(sacc[j][0]), tff(sacc[j][1]));
            *(float2*)&Ps[(w16 + grp + 8) * FQP + j * 8 + qid * 2] =
                make_float2(tff(sacc[j][2]), tff(sacc[j][3]));
        }
        __syncwarp();
        const uint32_t* uP = (const uint32_t*)Ps;
        const uint32_t* uV = (const uint32_t*)(Vs + buf * 64 * FVP);
        #pragma unroll
        for (int ks = 0; ks < 8; ks++) {
            int kk = ks * 8;
            uint32_t af[4];
            af[0] = uP[(w16 + grp    ) * FQP + kk + qid];
            af[1] = uP[(w16 + grp + 8) * FQP + kk + qid];
            af[2] = uP[(w16 + grp    ) * FQP + kk + qid + 4];
            af[3] = uP[(w16 + grp + 8) * FQP + kk + qid + 4];
            #pragma unroll
            for (int j = 0; j < 8; j++) {
                uint32_t bf[2];
                bf[0] = uV[(kk + qid    ) * FVP + j * 8 + grp];
                bf[1] = uV[(kk + qid + 4) * FVP + j * 8 + grp];
                mma_tf32(oacc[j], af, bf);
            }
        }
    }

    // ---- epilogue: normalize, row-mask, round, store
    int tl0 = qt * 128 + w16 + grp;
    float inv0 = 1.0f / l_[0], inv1 = 1.0f / l_[1];
    bool z0 = (tl0 >= len), z1 = (tl0 + 8 >= len);
    float* Og = o + ((long long)(b * NT + tl0)) * DM + h * DHS;
    #pragma unroll
    for (int j = 0; j < 8; j++) {
        int c = j * 8 + qid * 2;
        float2 v0, v1;
        v0.x = z0 ? 0.f : tff(oacc[j][0] * inv0);
        v0.y = z0 ? 0.f : tff(oacc[j][1] * inv0);
        v1.x = z1 ? 0.f : tff(oacc[j][2] * inv1);
        v1.y = z1 ? 0.f : tff(oacc[j][3] * inv1);
        *(float2*)(Og + c) = v0;
        *(float2*)(Og + (long long)8 * DM + c) = v1;
    }
}

// ---------------- pooling ----------------
__global__ void score_kernel(const float* __restrict__ xn,
                             const float* __restrict__ attn_w,
                             const float* __restrict__ attn_b,
                             float* __restrict__ scores) {
    __shared__ float red[32];
    int bt = blockIdx.x, tid = threadIdx.x;
    float4 xv = *(const float4*)(xn + (long long)bt * DM + tid * 4);
    float4 wv = *(const float4*)(attn_w + tid * 4);
    float s = xv.x*wv.x + xv.y*wv.y + xv.z*wv.z + xv.w*wv.w;
    s = blockReduceSum(s, red);
    if (tid == 0) scores[bt] = s + attn_b[0];
}

__global__ void pool_softmax_kernel(const float* __restrict__ scores,
                                    const int* __restrict__ lengths,
                                    float* __restrict__ aw) {
    __shared__ float red[32];
    int b = blockIdx.x, t = threadIdx.x;
    int len = lengths[b];
    float s = (t < len) ? scores[b * NT + t] : -3.0e38f;
    float m = blockReduceMax(s, red);
    float e = (t < len) ? expf(s - m) : 0.f;
    float sum = blockReduceSum(e, red);
    aw[b * NT + t] = e / sum;
}

__global__ void pool_sum_kernel(const float* __restrict__ xn,
                                const float* __restrict__ aw,
                                float* __restrict__ part) {
    int b = blockIdx.y, c = blockIdx.x, d = threadIdx.x;
    float acc = 0.f;
    int t0 = c * 128;
    for (int t = t0; t < t0 + 128; t++)
        acc += aw[b * NT + t] * xn[((long long)b * NT + t) * DM + d];
    part[(b * 8 + c) * DM + d] = acc;
}

__global__ void logits_kernel(const float* __restrict__ part,
                              const float* __restrict__ head_w,
                              const float* __restrict__ head_b,
                              float* __restrict__ out) {
    __shared__ float summ[DM];
    int b = blockIdx.x, o = threadIdx.x;
    for (int d = o; d < DM; d += 64) {
        float s = 0.f;
        for (int c = 0; c < 8; c++) s += part[(b * 8 + c) * DM + d];
        summ[d] = s;
    }
    __syncthreads();
    if (o < NO) {
        float acc = head_b[o];
        for (int d = 0; d < DM; d++) acc += summ[d] * head_w[d * NO + o];
        out[b * NO + o] = acc;
    }
}

// ---------------- host wrappers ----------------
#define SMEM128 ((3*128*AP + 3*32*(128+8)) * 4)   // 107520
#define SMEM64  ((3*128*AP + 3*32*(64+8))  * 4)   // 82944

static void gemm128(const float* A, const float* B, const float* bias, float* C,
                    int M, int N, int K, int lda, int ldb, int ldc,
                    long long aO, long long aI, long long bO, long long bI,
                    long long cO, long long cI, int zdiv, int z,
                    int flags, float alpha) {
    dim3 grid(N / 128, M / 128, z);
    gemm_tc_kernel<128, false><<<grid, 256, SMEM128>>>(A, B, bias, C, K, lda, ldb, ldc,
                                                       aO, aI, bO, bI, cO, cI, zdiv, flags, alpha);
}

extern "C" void kernel_launch(void* const* d_in, const int* in_sizes, int n_in,
                              void* d_out, int out_size) {
    const int*   code    = (const int*)  d_in[0];
    const int*   lengths = (const int*)  d_in[1];
    const float* emb     = (const float*)d_in[2];
    const float* Wq      = (const float*)d_in[3];
    const float* Wk      = (const float*)d_in[4];
    const float* Wv      = (const float*)d_in[5];
    const float* Wo      = (const float*)d_in[6];
    const float* bo      = (const float*)d_in[7];
    const float* W1      = (const float*)d_in[8];
    const float* b1      = (const float*)d_in[9];
    const float* W2      = (const float*)d_in[10];
    const float* b2      = (const float*)d_in[11];
    const float* ln1_g   = (const float*)d_in[12];
    const float* ln1_b   = (const float*)d_in[13];
    const float* ln2_g   = (const float*)d_in[14];
    const float* ln2_b   = (const float*)d_in[15];
    const float* lnf_g   = (const float*)d_in[16];
    const float* lnf_b   = (const float*)d_in[17];
    const float* attn_w  = (const float*)d_in[18];
    const float* attn_b  = (const float*)d_in[19];
    const float* head_w  = (const float*)d_in[20];
    const float* head_b  = (const float*)d_in[21];
    float* out = (float*)d_out;

    cudaFuncSetAttribute(gemm_tc_kernel<128, false>,
                         cudaFuncAttributeMaxDynamicSharedMemorySize, SMEM128);
    cudaFuncSetAttribute(flash_attn_kernel,
                         cudaFuncAttributeMaxDynamicSharedMemorySize, FA_SMEM);

    float *x, *xn, *q, *k, *v, *o, *h1, *scr, *aw, *part;
    float *Wrep, *WoR, *W1R, *W2R;
    cudaGetSymbolAddress((void**)&x,   g_x);
    cudaGetSymbolAddress((void**)&xn,  g_xn);
    cudaGetSymbolAddress((void**)&q,   g_q);
    cudaGetSymbolAddress((void**)&k,   g_k);
    cudaGetSymbolAddress((void**)&v,   g_v);
    cudaGetSymbolAddress((void**)&o,   g_o);
    cudaGetSymbolAddress((void**)&h1,  g_h1);
    cudaGetSymbolAddress((void**)&scr, g_scores);
    cudaGetSymbolAddress((void**)&aw,  g_aw);
    cudaGetSymbolAddress((void**)&part,g_part);
    cudaGetSymbolAddress((void**)&Wrep,g_Wrep);
    cudaGetSymbolAddress((void**)&WoR, g_WoR);
    cudaGetSymbolAddress((void**)&W1R, g_W1R);
    cudaGetSymbolAddress((void**)&W2R, g_W2R);

    const long long sWl = (long long)DM * DM;

    // repack + round all weights
    repack_kernel<<<dim3(NL * DM * DM / 256, 3), 256>>>(Wq, Wk, Wv, Wrep);
    roundcopy_kernel<<<(NL*DM*DM/4 + 255)/256, 256>>>(Wo, WoR, NL*DM*DM/4);
    roundcopy_kernel<<<(NL*DM*DFF/4 + 255)/256, 256>>>(W1, W1R, NL*DM*DFF/4);
    roundcopy_kernel<<<(NL*DFF*DM/4 + 255)/256, 256>>>(W2, W2R, NL*DFF*DM/4);

    embed_kernel<<<BT, 128>>>(code, emb, x);

    for (int l = 0; l < NL; l++) {
        const float* Wrq = Wrep + (long long)0 * NL * sWl + l * sWl;
        const float* Wrk = Wrep + (long long)1 * NL * sWl + l * sWl;
        const float* Wrv = Wrep + (long long)2 * NL * sWl + l * sWl;
        const float* Wol = WoR + (long long)l * DM * DM;
        const float* W1l = W1R + (long long)l * DM * DFF;
        const float* W2l = W2R + (long long)l * DFF * DM;

        ln_kernel<<<BT, 128>>>(x, ln1_g + l * DM, ln1_b + l * DM, xn, 1);

        // q/k/v = round(xn @ Wr*)  — all heads in one GEMM each
        gemm128(xn, Wrq, nullptr, q, BT, DM, DM, DM, DM, DM,
                0, 0, 0, 0, 0, 0, 1, 1, 16, 1.0f);
        gemm128(xn, Wrk, nullptr, k, BT, DM, DM, DM, DM, DM,
                0, 0, 0, 0, 0, 0, 1, 1, 16, 1.0f);
        gemm128(xn, Wrv, nullptr, v, BT, DM, DM, DM, DM, DM,
                0, 0, 0, 0, 0, 0, 1, 1, 16, 1.0f);

        // fused attention: o = softmax-mask(q k^T / 8) v
        flash_attn_kernel<<<dim3(NT / 128, NH, NB), 256, FA_SMEM>>>(q, k, v, lengths, o);

        // x += o @ Wo + bo
        gemm128(o, Wol, bo + l * DM, x, BT, DM, DM, DM, DM, DM,
                0, 0, 0, 0, 0, 0, 1, 1, 2 | 8, 1.0f);

        ln_kernel<<<BT, 128>>>(x, ln2_g + l * DM, ln2_b + l * DM, xn, 1);

        // h1 = round(gelu(xn @ W1 + b1))
        gemm128(xn, W1l, b1 + l * DFF, h1, BT, DFF, DM, DM, DFF, DFF,
                0, 0, 0, 0, 0, 0, 1, 1, 4 | 8 | 16, 1.0f);

        // x += h1 @ W2 + b2
        gemm128(h1, W2l, b2 + l * DM, x, BT, DM, DFF, DFF, DM, DM,
                0, 0, 0, 0, 0, 0, 1, 1, 2 | 8, 1.0f);
    }

    ln_kernel<<<BT, 128>>>(x, lnf_g, lnf_b, xn, 0);
    score_kernel<<<BT, 128>>>(xn, attn_w, attn_b, scr);
    pool_softmax_kernel<<<NB, 1024>>>(scr, lengths, aw);
    pool_sum_kernel<<<dim3(8, NB), 512>>>(xn, aw, part);
    logits_kernel<<<NB, 64>>>(part, head_w, head_b, out);
}